// round 13
// baseline (speedup 1.0000x reference)
#include <cuda_runtime.h>
#include <cuda_bf16.h>
#include <stdint.h>
#include <math.h>

#define BSZ 32
#define CSZ 256
#define HH  56
#define WFQ 32
#define WWK 62
#define NPIX 3136
#define MSZ 16
#define KSZ 8
#define HIDN 16
#define PI_D 3.141592653589793238462643383279502884

typedef unsigned long long ull;

__device__ __forceinline__ ull d_fma2(ull a, ull b, ull c) {
    ull d;
    asm("fma.rn.f32x2 %0, %1, %2, %3;" : "=l"(d) : "l"(a), "l"(b), "l"(c));
    return d;
}
__device__ __forceinline__ ull d_dup(float x) {
    ull r;
    asm("mov.b64 %0, {%1, %1};" : "=l"(r) : "f"(x));
    return r;
}
__device__ __forceinline__ float2 d_unpack(ull v) {
    float2 r;
    asm("mov.b64 {%0, %1}, %2;" : "=f"(r.x), "=f"(r.y) : "l"(v));
    return r;
}
__device__ __forceinline__ void mma_bf16(float* d, const uint32_t* a, const uint32_t* b) {
    asm("mma.sync.aligned.m16n8k16.row.col.f32.bf16.bf16.f32 "
        "{%0,%1,%2,%3}, {%4,%5,%6,%7}, {%8,%9}, {%0,%1,%2,%3};"
        : "+f"(d[0]), "+f"(d[1]), "+f"(d[2]), "+f"(d[3])
        : "r"(a[0]), "r"(a[1]), "r"(a[2]), "r"(a[3]), "r"(b[0]), "r"(b[1]));
}
__device__ __forceinline__ void bsplit(float v, __nv_bfloat16& hi, __nv_bfloat16& lo) {
    hi = __float2bfloat16(v);
    lo = __float2bfloat16(v - __bfloat162float(hi));
}
__device__ __forceinline__ void lda_frags(const __nv_bfloat16* P, int stride, int r0, int cb, uint32_t* f) {
    f[0] = *(const uint32_t*)&P[r0 * stride + cb];
    f[1] = *(const uint32_t*)&P[(r0 + 8) * stride + cb];
    f[2] = *(const uint32_t*)&P[r0 * stride + cb + 8];
    f[3] = *(const uint32_t*)&P[(r0 + 8) * stride + cb + 8];
}
__device__ __forceinline__ void ldb_frag(const __nv_bfloat16* P, int stride, int n0, int cb, uint32_t* f) {
    f[0] = *(const uint32_t*)&P[n0 * stride + cb];
    f[1] = *(const uint32_t*)&P[n0 * stride + cb + 8];
}

// ----------------------------- device scratch -------------------------------
__device__ float  g_ctx[BSZ * CSZ];
__device__ float  g_hact[BSZ * HIDN];
__device__ float  g_coeffs[BSZ * CSZ * MSZ * KSZ];
__device__ float  g_yspec[(size_t)BSZ * CSZ * NPIX];
__device__ float  g_bnA[CSZ], g_bnB[CSZ];
__device__ float  g_s1[CSZ], g_s2[CSZ];
__device__ __nv_bfloat16 g_whl[2][CSZ * CSZ];

__device__ float2 g_FwRT[HH * WFQ];
__device__ float2 g_Fh[HH * HH];
__device__ float2 g_Gh[HH * HH];
__device__ float2 g_GwT[WFQ * HH];

__device__ double g_Rf[WWK * HH];
__device__ double g_Rb[HH * WWK];
__device__ double g_tw62r[WWK], g_tw62i[WWK];

__device__ double rz_fwd(int j, int i) {
    double s = (j + 0.5) * (56.0 / 62.0) - 0.5;
    double w = fmax(0.0, 1.0 - fabs(s - (double)i));
    double denom = 0.0;
    int i0 = (int)floor(s);
    for (int q = i0; q <= i0 + 1; ++q)
        if (q >= 0 && q < 56) denom += fmax(0.0, 1.0 - fabs(s - (double)q));
    return w / denom;
}
__device__ double rz_bwd(int j, int i) {
    double ks = 62.0 / 56.0;
    double s = (j + 0.5) * ks - 0.5;
    double w = fmax(0.0, 1.0 - fabs(s - (double)i) / ks);
    double denom = 0.0;
    int lo = (int)ceil(s - ks), hi = (int)floor(s + ks);
    if (lo < 0) lo = 0;
    if (hi > 61) hi = 61;
    for (int q = lo; q <= hi; ++q)
        denom += fmax(0.0, 1.0 - fabs(s - (double)q) / ks);
    return w / denom;
}

__global__ void k_init0() {
    int t = threadIdx.x;
    if (t < WWK) { double a = -2.0 * PI_D * t / 62.0; g_tw62r[t] = cos(a); g_tw62i[t] = sin(a); }
    for (int i = t; i < WWK * HH; i += blockDim.x) g_Rf[i] = rz_fwd(i / HH, i % HH);
    for (int i = t; i < HH * WWK; i += blockDim.x) g_Rb[i] = rz_bwd(i / WWK, i % WWK);
}

__global__ void k_init1() {
    const double SC = 1.0 / sqrt(56.0 * 62.0);
    int total = 1792 + 1792 + 3136 + 3136;
    for (int idx = blockIdx.x * blockDim.x + threadIdx.x; idx < total; idx += gridDim.x * blockDim.x) {
        if (idx < 1792) {
            int w0 = idx / WFQ, v = idx % WFQ;
            double ar = 0, ai = 0;
            for (int w = 0; w < WWK; ++w) {
                double r = g_Rf[w * HH + w0]; int m = (v * w) % WWK;
                ar += g_tw62r[m] * r; ai += g_tw62i[m] * r;
            }
            g_FwRT[w0 * WFQ + v] = make_float2((float)(ar * SC), (float)(ai * SC));
        } else if (idx < 3584) {
            int j = idx - 1792; int v = j / HH, w0 = j % HH;
            double cv = (v == 0 || v == 31) ? 1.0 : 2.0;
            double ar = 0, ai = 0;
            for (int w = 0; w < WWK; ++w) {
                double r = g_Rb[w0 * WWK + w]; int m = (v * w) % WWK;
                ar += g_tw62r[m] * r; ai -= g_tw62i[m] * r;
            }
            g_GwT[v * HH + w0] = make_float2((float)(ar * cv * SC), (float)(ai * cv * SC));
        } else if (idx < 6720) {
            int j = idx - 3584; int u = j / HH, h = j % HH;
            double a = -2.0 * PI_D * ((u * h) % HH) / 56.0;
            g_Fh[u * HH + h] = make_float2((float)cos(a), (float)sin(a));
        } else {
            int j = idx - 6720; int h = j / HH, u = j % HH;
            double a = 2.0 * PI_D * ((u * h) % HH) / 56.0;
            g_Gh[h * HH + u] = make_float2((float)cos(a), (float)(sin(a)));
        }
    }
}

__global__ void k_ctx(const float* __restrict__ x) {
    int plane = blockIdx.x;
    const float4* p = (const float4*)(x + (size_t)plane * NPIX);
    float s = 0.f;
    for (int i = threadIdx.x; i < NPIX / 4; i += blockDim.x) {
        float4 v = p[i]; s += v.x + v.y + v.z + v.w;
    }
    for (int o = 16; o > 0; o >>= 1) s += __shfl_xor_sync(0xffffffffu, s, o);
    __shared__ float red[4];
    int warp = threadIdx.x >> 5, lane = threadIdx.x & 31;
    if (lane == 0) red[warp] = s;
    __syncthreads();
    if (threadIdx.x == 0)
        g_ctx[plane] = (red[0] + red[1] + red[2] + red[3]) * (1.0f / NPIX);
}

__global__ void __launch_bounds__(256) k_head1(
    const float* __restrict__ fc1_w, const float* __restrict__ fc1_b,
    const float* __restrict__ ln_g,  const float* __restrict__ ln_b)
{
    int b = blockIdx.x, t = threadIdx.x;
    int warp = t >> 5, lane = t & 31;
    __shared__ float sctx[CSZ];
    __shared__ float shid[HIDN];
    __shared__ float sstat[2];
    sctx[t] = g_ctx[b * CSZ + t];
    __syncthreads();
    for (int rep = 0; rep < 2; ++rep) {
        int hidx = warp * 2 + rep;
        float acc = 0.f;
        for (int c = lane; c < CSZ; c += 32) acc += sctx[c] * fc1_w[hidx * CSZ + c];
        for (int o = 16; o > 0; o >>= 1) acc += __shfl_xor_sync(0xffffffffu, acc, o);
        if (lane == 0) shid[hidx] = acc + fc1_b[hidx];
    }
    __syncthreads();
    if (t == 0) {
        float mu = 0.f;
        for (int i = 0; i < HIDN; ++i) mu += shid[i];
        mu *= (1.0f / HIDN);
        float var = 0.f;
        for (int i = 0; i < HIDN; ++i) { float d = shid[i] - mu; var += d * d; }
        sstat[0] = mu; sstat[1] = rsqrtf(var * (1.0f / HIDN) + 1e-5f);
    }
    __syncthreads();
    if (t < HIDN)
        g_hact[b * HIDN + t] =
            fmaxf((shid[t] - sstat[0]) * sstat[1] * ln_g[t] + ln_b[t], 0.f);
}

__global__ void __launch_bounds__(256) k_head2(
    const float* __restrict__ fh_w, const float* __restrict__ fh_b)
{
    __shared__ float sH[BSZ * 17];
    int t = threadIdx.x;
    for (int i = t; i < BSZ * HIDN; i += 256)
        sH[(i >> 4) * 17 + (i & 15)] = g_hact[i];
    __syncthreads();
    int b = t & 31;
    int grp = blockIdx.x * 8 + (t >> 5);
    float h[HIDN];
#pragma unroll
    for (int i = 0; i < HIDN; ++i) h[i] = sH[b * 17 + i];

    const float4* wp = (const float4*)(fh_w + (size_t)grp * KSZ * HIDN);
    float lg[KSZ]; float mx = -1e30f;
#pragma unroll
    for (int k = 0; k < KSZ; ++k) {
        float4 w0 = wp[k * 4 + 0], w1 = wp[k * 4 + 1], w2 = wp[k * 4 + 2], w3 = wp[k * 4 + 3];
        float a = fh_b[grp * KSZ + k];
        a += h[0]*w0.x + h[1]*w0.y + h[2]*w0.z + h[3]*w0.w;
        a += h[4]*w1.x + h[5]*w1.y + h[6]*w1.z + h[7]*w1.w;
        a += h[8]*w2.x + h[9]*w2.y + h[10]*w2.z + h[11]*w2.w;
        a += h[12]*w3.x + h[13]*w3.y + h[14]*w3.z + h[15]*w3.w;
        lg[k] = a; mx = fmaxf(mx, a);
    }
    float sum = 0.f;
#pragma unroll
    for (int k = 0; k < KSZ; ++k) { lg[k] = expf(lg[k] - mx); sum += lg[k]; }
    float inv = 1.0f / sum;
    float* out = g_coeffs + (size_t)b * (CSZ * MSZ * KSZ) + grp * KSZ;
    ((float4*)out)[0] = make_float4(lg[0]*inv, lg[1]*inv, lg[2]*inv, lg[3]*inv);
    ((float4*)out)[1] = make_float4(lg[4]*inv, lg[5]*inv, lg[6]*inv, lg[7]*inv);
}

// per-plane fused resize/DFT/mask/iDFT/resize (R4/R7 scalar f32x2, inline mask)
__global__ void __launch_bounds__(256) k_spec(
    const float* __restrict__ x,
    const float* __restrict__ br, const float* __restrict__ bi)
{
    __shared__ __align__(16) float sm[10432];
    float2* B1 = (float2*)sm;
    float2* B2 = (float2*)(sm + 3584);
    float*  BX = sm + 7168;
    float4* Bq = (float4*)(sm + 7168);
    float*  sCo = sm + 10304;

    int plane = blockIdx.x;
    int t = threadIdx.x, warp = t >> 5, lane = t & 31;
    const float* xp = x + (size_t)plane * NPIX;

    for (int i = t; i < NPIX; i += 256) BX[i] = xp[i];
    if (t < 128) sCo[t] = g_coeffs[(size_t)plane * 128 + t];
    for (int i = t; i < 1792; i += 256) B1[i] = g_FwRT[i];
    __syncthreads();

    {
        float2 acc[7];
#pragma unroll
        for (int r = 0; r < 7; ++r) acc[r] = make_float2(0.f, 0.f);
        int h0 = warp * 7;
        for (int w = 0; w < HH; w += 2) {
            float2 f0 = B1[w * WFQ + lane];
            float2 f1 = B1[(w + 1) * WFQ + lane];
#pragma unroll
            for (int r = 0; r < 7; ++r) {
                float2 a = *(const float2*)&BX[(h0 + r) * HH + w];
                acc[r].x += a.x * f0.x + a.y * f1.x;
                acc[r].y += a.x * f0.y + a.y * f1.y;
            }
        }
#pragma unroll
        for (int r = 0; r < 7; ++r) B2[(h0 + r) * WFQ + lane] = acc[r];
    }
    __syncthreads();

    for (int half = 0; half < 2; ++half) {
        int ub = half * 28;
        for (int i = t; i < 14 * HH; i += 256) {
            int p = i / HH, h = i % HH;
            float2 f0 = g_Fh[(ub + 2 * p) * HH + h];
            float2 f1 = g_Fh[(ub + 2 * p + 1) * HH + h];
            Bq[i] = make_float4(f0.x, f1.x, f0.y, f1.y);
        }
        __syncthreads();
        ull ar[2] = {0, 0}, ai[2] = {0, 0};
        int p1ok = (warp + 8) < 14;
        for (int h = 0; h < HH; ++h) {
            float2 tt = B2[h * WFQ + lane];
            ull ttx = d_dup(tt.x), tty = d_dup(tt.y), ttyn = d_dup(-tt.y);
            float4 q0 = Bq[warp * HH + h];
            ull fx0 = *(ull*)&q0.x, fy0 = *(ull*)&q0.z;
            ar[0] = d_fma2(fx0, ttx, ar[0]); ar[0] = d_fma2(fy0, ttyn, ar[0]);
            ai[0] = d_fma2(fy0, ttx, ai[0]); ai[0] = d_fma2(fx0, tty, ai[0]);
            if (p1ok) {
                float4 q1 = Bq[(warp + 8) * HH + h];
                ull fx1 = *(ull*)&q1.x, fy1 = *(ull*)&q1.z;
                ar[1] = d_fma2(fx1, ttx, ar[1]); ar[1] = d_fma2(fy1, ttyn, ar[1]);
                ai[1] = d_fma2(fy1, ttx, ai[1]); ai[1] = d_fma2(fx1, tty, ai[1]);
            }
        }
#pragma unroll
        for (int pp = 0; pp < 2; ++pp) {
            int p = warp + 8 * pp;
            if (p < 14) {
                float2 re = d_unpack(ar[pp]), im = d_unpack(ai[pp]);
#pragma unroll
                for (int j = 0; j < 2; ++j) {
                    int u = ub + 2 * p + j;
                    const float* co = sCo + ((u / 14) * 4 + (lane >> 3)) * KSZ;
                    float mr = 0.f, mi = 0.f;
#pragma unroll
                    for (int k = 0; k < KSZ; ++k) {
                        int bidx = k * (HH * WFQ) + u * WFQ + lane;
                        mr += co[k] * br[bidx];
                        mi += co[k] * bi[bidx];
                    }
                    float xr = j ? re.y : re.x, xi = j ? im.y : im.x;
                    B1[u * WFQ + lane] = make_float2(xr * mr - xi * mi, xr * mi + xi * mr);
                }
            }
        }
        __syncthreads();
    }

    for (int half = 0; half < 2; ++half) {
        int hb = half * 28;
        for (int i = t; i < 14 * HH; i += 256) {
            int p = i / HH, u = i % HH;
            float2 f0 = g_Gh[(hb + 2 * p) * HH + u];
            float2 f1 = g_Gh[(hb + 2 * p + 1) * HH + u];
            Bq[i] = make_float4(f0.x, f1.x, f0.y, f1.y);
        }
        __syncthreads();
        ull ar[2] = {0, 0}, ai[2] = {0, 0};
        int p1ok = (warp + 8) < 14;
        for (int u = 0; u < HH; ++u) {
            float2 yy = B1[u * WFQ + lane];
            ull yx = d_dup(yy.x), yyp = d_dup(yy.y), yyn = d_dup(-yy.y);
            float4 q0 = Bq[warp * HH + u];
            ull fx0 = *(ull*)&q0.x, fy0 = *(ull*)&q0.z;
            ar[0] = d_fma2(fx0, yx, ar[0]); ar[0] = d_fma2(fy0, yyn, ar[0]);
            ai[0] = d_fma2(fy0, yx, ai[0]); ai[0] = d_fma2(fx0, yyp, ai[0]);
            if (p1ok) {
                float4 q1 = Bq[(warp + 8) * HH + u];
                ull fx1 = *(ull*)&q1.x, fy1 = *(ull*)&q1.z;
                ar[1] = d_fma2(fx1, yx, ar[1]); ar[1] = d_fma2(fy1, yyn, ar[1]);
                ai[1] = d_fma2(fy1, yx, ai[1]); ai[1] = d_fma2(fx1, yyp, ai[1]);
            }
        }
#pragma unroll
        for (int pp = 0; pp < 2; ++pp) {
            int p = warp + 8 * pp;
            if (p < 14) {
                float2 re = d_unpack(ar[pp]), im = d_unpack(ai[pp]);
                B2[(hb + 2 * p + 0) * WFQ + lane] = make_float2(re.x, im.x);
                B2[(hb + 2 * p + 1) * WFQ + lane] = make_float2(re.y, im.y);
            }
        }
        __syncthreads();
    }

    for (int i = t; i < 1792; i += 256) B1[i] = g_GwT[i];
    __syncthreads();
    float* outp = g_yspec + (size_t)plane * NPIX;
    for (int grp = 0; grp < 2; ++grp) {
        int nr = grp ? 3 : 4;
        float a1[4] = {0.f, 0.f, 0.f, 0.f};
        float a2[4] = {0.f, 0.f, 0.f, 0.f};
        for (int v = 0; v < WFQ; ++v) {
            float2 g1 = B1[v * HH + lane];
            float2 g2 = (lane < 24) ? B1[v * HH + 32 + lane] : make_float2(0.f, 0.f);
#pragma unroll
            for (int r = 0; r < 4; ++r) {
                if (r < nr) {
                    float2 tt = B2[(warp + 8 * (grp * 4 + r)) * WFQ + v];
                    a1[r] += tt.x * g1.x - tt.y * g1.y;
                    a2[r] += tt.x * g2.x - tt.y * g2.y;
                }
            }
        }
#pragma unroll
        for (int r = 0; r < 4; ++r) {
            if (r < nr) {
                int h = warp + 8 * (grp * 4 + r);
                outp[h * HH + lane] = a1[r];
                if (lane < 24) outp[h * HH + 32 + lane] = a2[r];
            }
        }
    }
}

// W -> bf16 hi/lo split; block 0 also zeroes BN accumulators
__global__ void k_wsplit(const float* __restrict__ W) {
    int i = blockIdx.x * blockDim.x + threadIdx.x;
    float v = W[i];
    __nv_bfloat16 hi = __float2bfloat16(v);
    __nv_bfloat16 lo = __float2bfloat16(v - __bfloat162float(hi));
    g_whl[0][i] = hi;
    g_whl[1][i] = lo;
    if (blockIdx.x == 0) { g_s1[threadIdx.x] = 0.f; g_s2[threadIdx.x] = 0.f; }
}

// ----- 1x1 conv via mma.sync bf16 split (R11 tile config, two-pass) --------
// mode 0: accumulate BN sums only (no stores)
// mode 1: apply BN (g_bnA/g_bnB) and write directly to out
#define KC 32
#define ASTR 40
__global__ void __launch_bounds__(256) k_conv_mma(int mode, float* __restrict__ out) {
    __shared__ __nv_bfloat16 cAh[128 * ASTR];
    __shared__ __nv_bfloat16 cAl[128 * ASTR];
    __shared__ __nv_bfloat16 cBh[128 * ASTR];
    __shared__ __nv_bfloat16 cBl[128 * ASTR];
    __shared__ float sS1[128], sS2[128];

    int t = threadIdx.x, wid = t >> 5, lane = t & 31;
    int p0 = blockIdx.x * 128;
    int mo = blockIdx.y * 128;
    int b  = blockIdx.z;
    const float* Y = g_yspec + (size_t)b * CSZ * NPIX;

    int wm = (wid & 1) * 64;
    int wn = (wid >> 1) * 32;
    int qr = lane >> 2, qc = lane & 3;

    if (mode == 0 && t < 128) { sS1[t] = 0.f; sS2[t] = 0.f; }

    float acc[16][4];
#pragma unroll
    for (int i = 0; i < 16; ++i)
#pragma unroll
        for (int j = 0; j < 4; ++j) acc[i][j] = 0.f;

    for (int kk = 0; kk < CSZ; kk += KC) {
        {
            int r = t >> 1, cg = (t & 1) * 16;
            const __nv_bfloat16* w0 = &g_whl[0][(size_t)(mo + r) * CSZ + kk + cg];
            const __nv_bfloat16* w1 = &g_whl[1][(size_t)(mo + r) * CSZ + kk + cg];
            *(uint4*)&cAh[r * ASTR + cg]     = *(const uint4*)w0;
            *(uint4*)&cAh[r * ASTR + cg + 8] = *(const uint4*)(w0 + 8);
            *(uint4*)&cAl[r * ASTR + cg]     = *(const uint4*)w1;
            *(uint4*)&cAl[r * ASTR + cg + 8] = *(const uint4*)(w1 + 8);
        }
        {
            int c = t >> 3, pg2 = (t & 7) * 16;
#pragma unroll
            for (int j = 0; j < 16; j += 4) {
                float4 v = make_float4(0.f, 0.f, 0.f, 0.f);
                if (p0 + pg2 + j < NPIX)
                    v = *(const float4*)&Y[(size_t)(kk + c) * NPIX + p0 + pg2 + j];
                float vv[4] = {v.x, v.y, v.z, v.w};
#pragma unroll
                for (int e = 0; e < 4; ++e) {
                    __nv_bfloat16 hi, lo; bsplit(vv[e], hi, lo);
                    cBh[(pg2 + j + e) * ASTR + c] = hi;
                    cBl[(pg2 + j + e) * ASTR + c] = lo;
                }
            }
        }
        __syncthreads();

#pragma unroll
        for (int ks = 0; ks < 2; ++ks) {
            int cb = ks * 16 + qc * 2;
            uint32_t afh[4][4], afl[4][4];
#pragma unroll
            for (int mf = 0; mf < 4; ++mf) {
                lda_frags(cAh, ASTR, wm + mf * 16 + qr, cb, afh[mf]);
                lda_frags(cAl, ASTR, wm + mf * 16 + qr, cb, afl[mf]);
            }
            uint32_t bf[4][2];
#pragma unroll
            for (int nf = 0; nf < 4; ++nf)
                ldb_frag(cBh, ASTR, wn + nf * 8 + qr, cb, bf[nf]);
#pragma unroll
            for (int mf = 0; mf < 4; ++mf)
#pragma unroll
                for (int nf = 0; nf < 4; ++nf) {
                    mma_bf16(acc[mf * 4 + nf], afh[mf], bf[nf]);
                    mma_bf16(acc[mf * 4 + nf], afl[mf], bf[nf]);
                }
#pragma unroll
            for (int nf = 0; nf < 4; ++nf)
                ldb_frag(cBl, ASTR, wn + nf * 8 + qr, cb, bf[nf]);
#pragma unroll
            for (int mf = 0; mf < 4; ++mf)
#pragma unroll
                for (int nf = 0; nf < 4; ++nf)
                    mma_bf16(acc[mf * 4 + nf], afh[mf], bf[nf]);
        }
        __syncthreads();
    }

    if (mode == 0) {
        // BN partial sums only
#pragma unroll
        for (int mf = 0; mf < 4; ++mf) {
            float s1a = 0.f, s2a = 0.f, s1b = 0.f, s2b = 0.f;
#pragma unroll
            for (int nf = 0; nf < 4; ++nf) {
                float* a = acc[mf * 4 + nf];
                s1a += a[0] + a[1]; s2a += a[0]*a[0] + a[1]*a[1];
                s1b += a[2] + a[3]; s2b += a[2]*a[2] + a[3]*a[3];
            }
#pragma unroll
            for (int o = 1; o <= 2; o <<= 1) {
                s1a += __shfl_xor_sync(0xffffffffu, s1a, o);
                s2a += __shfl_xor_sync(0xffffffffu, s2a, o);
                s1b += __shfl_xor_sync(0xffffffffu, s1b, o);
                s2b += __shfl_xor_sync(0xffffffffu, s2b, o);
            }
            if (qc == 0) {
                int lr = wm + mf * 16 + qr;
                atomicAdd(&sS1[lr], s1a); atomicAdd(&sS2[lr], s2a);
                atomicAdd(&sS1[lr + 8], s1b); atomicAdd(&sS2[lr + 8], s2b);
            }
        }
        __syncthreads();
        if (t < 128) {
            atomicAdd(&g_s1[mo + t], sS1[t]);
            atomicAdd(&g_s2[mo + t], sS2[t]);
        }
    } else {
        // apply BN, write d_out directly
        float* Outb = out + (size_t)b * CSZ * NPIX;
#pragma unroll
        for (int mf = 0; mf < 4; ++mf) {
            int r = mo + wm + mf * 16 + qr;
            float A0 = g_bnA[r], B0 = g_bnB[r];
            float A1 = g_bnA[r + 8], B1v = g_bnB[r + 8];
#pragma unroll
            for (int nf = 0; nf < 4; ++nf) {
                float* a = acc[mf * 4 + nf];
                int cl = p0 + wn + nf * 8 + qc * 2;
                if (cl < NPIX) {
                    *(float2*)&Outb[(size_t)r * NPIX + cl] =
                        make_float2(a[0] * A0 + B0, a[1] * A0 + B0);
                    *(float2*)&Outb[(size_t)(r + 8) * NPIX + cl] =
                        make_float2(a[2] * A1 + B1v, a[3] * A1 + B1v);
                }
            }
        }
    }
}

__global__ void k_bnfin(const float* __restrict__ bn_g, const float* __restrict__ bn_b) {
    int o = threadIdx.x;
    double N = (double)BSZ * NPIX;
    double mean = (double)g_s1[o] / N;
    double var = (double)g_s2[o] / N - mean * mean;
    float A = bn_g[o] * (float)(1.0 / sqrt(var + 1e-5));
    g_bnA[o] = A;
    g_bnB[o] = bn_b[o] - (float)mean * A;
}

extern "C" void kernel_launch(void* const* d_in, const int* in_sizes, int n_in,
                              void* d_out, int out_size) {
    const float* x      = (const float*)d_in[0];
    const float* fc1_w  = (const float*)d_in[1];
    const float* fc1_b  = (const float*)d_in[2];
    const float* ln_g   = (const float*)d_in[3];
    const float* ln_b   = (const float*)d_in[4];
    const float* fh_w   = (const float*)d_in[5];
    const float* fh_b   = (const float*)d_in[6];
    const float* br     = (const float*)d_in[7];
    const float* bi     = (const float*)d_in[8];
    const float* conv_w = (const float*)d_in[9];
    const float* bn_g   = (const float*)d_in[10];
    const float* bn_b   = (const float*)d_in[11];
    (void)in_sizes; (void)n_in; (void)out_size;

    k_init0<<<1, 256>>>();
    k_init1<<<40, 256>>>();
    k_ctx<<<BSZ * CSZ, 128>>>(x);
    k_head1<<<BSZ, 256>>>(fc1_w, fc1_b, ln_g, ln_b);
    k_head2<<<512, 256>>>(fh_w, fh_b);
    k_wsplit<<<256, 256>>>(conv_w);
    k_spec<<<BSZ * CSZ, 256>>>(x, br, bi);
    dim3 gc(25, 2, BSZ);
    k_conv_mma<<<gc, 256>>>(0, nullptr);
    k_bnfin<<<1, 256>>>(bn_g, bn_b);
    k_conv_mma<<<gc, 256>>>(1, (float*)d_out);
}

// round 14
// speedup vs baseline: 1.0798x; 1.0798x over previous
#include <cuda_runtime.h>
#include <cuda_bf16.h>
#include <stdint.h>
#include <math.h>

#define BSZ 32
#define CSZ 256
#define HH  56
#define WFQ 32
#define WWK 62
#define NPIX 3136
#define MSZ 16
#define KSZ 8
#define HIDN 16
#define PI_D 3.141592653589793238462643383279502884

typedef unsigned long long ull;

__device__ __forceinline__ ull d_fma2(ull a, ull b, ull c) {
    ull d;
    asm("fma.rn.f32x2 %0, %1, %2, %3;" : "=l"(d) : "l"(a), "l"(b), "l"(c));
    return d;
}
__device__ __forceinline__ ull d_dup(float x) {
    ull r;
    asm("mov.b64 %0, {%1, %1};" : "=l"(r) : "f"(x));
    return r;
}
__device__ __forceinline__ float2 d_unpack(ull v) {
    float2 r;
    asm("mov.b64 {%0, %1}, %2;" : "=f"(r.x), "=f"(r.y) : "l"(v));
    return r;
}
__device__ __forceinline__ void mma_bf16(float* d, const uint32_t* a, const uint32_t* b) {
    asm("mma.sync.aligned.m16n8k16.row.col.f32.bf16.bf16.f32 "
        "{%0,%1,%2,%3}, {%4,%5,%6,%7}, {%8,%9}, {%0,%1,%2,%3};"
        : "+f"(d[0]), "+f"(d[1]), "+f"(d[2]), "+f"(d[3])
        : "r"(a[0]), "r"(a[1]), "r"(a[2]), "r"(a[3]), "r"(b[0]), "r"(b[1]));
}
__device__ __forceinline__ void bsplit(float v, __nv_bfloat16& hi, __nv_bfloat16& lo) {
    hi = __float2bfloat16(v);
    lo = __float2bfloat16(v - __bfloat162float(hi));
}
__device__ __forceinline__ void lda_frags(const __nv_bfloat16* P, int stride, int r0, int cb, uint32_t* f) {
    f[0] = *(const uint32_t*)&P[r0 * stride + cb];
    f[1] = *(const uint32_t*)&P[(r0 + 8) * stride + cb];
    f[2] = *(const uint32_t*)&P[r0 * stride + cb + 8];
    f[3] = *(const uint32_t*)&P[(r0 + 8) * stride + cb + 8];
}
__device__ __forceinline__ void ldb_frag(const __nv_bfloat16* P, int stride, int n0, int cb, uint32_t* f) {
    f[0] = *(const uint32_t*)&P[n0 * stride + cb];
    f[1] = *(const uint32_t*)&P[n0 * stride + cb + 8];
}

// ----------------------------- device scratch -------------------------------
__device__ float  g_ctx[BSZ * CSZ];
__device__ float  g_hact[BSZ * HIDN];
__device__ float  g_coeffs[BSZ * CSZ * MSZ * KSZ];
__device__ __nv_bfloat16 g_yh[(size_t)BSZ * CSZ * NPIX];
__device__ __nv_bfloat16 g_yl[(size_t)BSZ * CSZ * NPIX];
__device__ float  g_yconv[(size_t)BSZ * CSZ * NPIX];
__device__ float  g_bnA[CSZ], g_bnB[CSZ];
__device__ float  g_s1[CSZ], g_s2[CSZ];
__device__ __nv_bfloat16 g_whl[2][CSZ * CSZ];

__device__ float2 g_FwRT[HH * WFQ];
__device__ float2 g_Fh[HH * HH];
__device__ float2 g_Gh[HH * HH];
__device__ float2 g_GwT[WFQ * HH];

__device__ double g_Rf[WWK * HH];
__device__ double g_Rb[HH * WWK];
__device__ double g_tw62r[WWK], g_tw62i[WWK];

__device__ double rz_fwd(int j, int i) {
    double s = (j + 0.5) * (56.0 / 62.0) - 0.5;
    double w = fmax(0.0, 1.0 - fabs(s - (double)i));
    double denom = 0.0;
    int i0 = (int)floor(s);
    for (int q = i0; q <= i0 + 1; ++q)
        if (q >= 0 && q < 56) denom += fmax(0.0, 1.0 - fabs(s - (double)q));
    return w / denom;
}
__device__ double rz_bwd(int j, int i) {
    double ks = 62.0 / 56.0;
    double s = (j + 0.5) * ks - 0.5;
    double w = fmax(0.0, 1.0 - fabs(s - (double)i) / ks);
    double denom = 0.0;
    int lo = (int)ceil(s - ks), hi = (int)floor(s + ks);
    if (lo < 0) lo = 0;
    if (hi > 61) hi = 61;
    for (int q = lo; q <= hi; ++q)
        denom += fmax(0.0, 1.0 - fabs(s - (double)q) / ks);
    return w / denom;
}

__global__ void k_init0() {
    int t = threadIdx.x;
    if (t < WWK) { double a = -2.0 * PI_D * t / 62.0; g_tw62r[t] = cos(a); g_tw62i[t] = sin(a); }
    for (int i = t; i < WWK * HH; i += blockDim.x) g_Rf[i] = rz_fwd(i / HH, i % HH);
    for (int i = t; i < HH * WWK; i += blockDim.x) g_Rb[i] = rz_bwd(i / WWK, i % WWK);
}

__global__ void k_init1() {
    const double SC = 1.0 / sqrt(56.0 * 62.0);
    int total = 1792 + 1792 + 3136 + 3136;
    for (int idx = blockIdx.x * blockDim.x + threadIdx.x; idx < total; idx += gridDim.x * blockDim.x) {
        if (idx < 1792) {
            int w0 = idx / WFQ, v = idx % WFQ;
            double ar = 0, ai = 0;
            for (int w = 0; w < WWK; ++w) {
                double r = g_Rf[w * HH + w0]; int m = (v * w) % WWK;
                ar += g_tw62r[m] * r; ai += g_tw62i[m] * r;
            }
            g_FwRT[w0 * WFQ + v] = make_float2((float)(ar * SC), (float)(ai * SC));
        } else if (idx < 3584) {
            int j = idx - 1792; int v = j / HH, w0 = j % HH;
            double cv = (v == 0 || v == 31) ? 1.0 : 2.0;
            double ar = 0, ai = 0;
            for (int w = 0; w < WWK; ++w) {
                double r = g_Rb[w0 * WWK + w]; int m = (v * w) % WWK;
                ar += g_tw62r[m] * r; ai -= g_tw62i[m] * r;
            }
            g_GwT[v * HH + w0] = make_float2((float)(ar * cv * SC), (float)(ai * cv * SC));
        } else if (idx < 6720) {
            int j = idx - 3584; int u = j / HH, h = j % HH;
            double a = -2.0 * PI_D * ((u * h) % HH) / 56.0;
            g_Fh[u * HH + h] = make_float2((float)cos(a), (float)sin(a));
        } else {
            int j = idx - 6720; int h = j / HH, u = j % HH;
            double a = 2.0 * PI_D * ((u * h) % HH) / 56.0;
            g_Gh[h * HH + u] = make_float2((float)cos(a), (float)(sin(a)));
        }
    }
}

__global__ void k_ctx(const float* __restrict__ x) {
    int plane = blockIdx.x;
    const float4* p = (const float4*)(x + (size_t)plane * NPIX);
    float s = 0.f;
    for (int i = threadIdx.x; i < NPIX / 4; i += blockDim.x) {
        float4 v = p[i]; s += v.x + v.y + v.z + v.w;
    }
    for (int o = 16; o > 0; o >>= 1) s += __shfl_xor_sync(0xffffffffu, s, o);
    __shared__ float red[4];
    int warp = threadIdx.x >> 5, lane = threadIdx.x & 31;
    if (lane == 0) red[warp] = s;
    __syncthreads();
    if (threadIdx.x == 0)
        g_ctx[plane] = (red[0] + red[1] + red[2] + red[3]) * (1.0f / NPIX);
}

__global__ void __launch_bounds__(256) k_head1(
    const float* __restrict__ fc1_w, const float* __restrict__ fc1_b,
    const float* __restrict__ ln_g,  const float* __restrict__ ln_b)
{
    int b = blockIdx.x, t = threadIdx.x;
    int warp = t >> 5, lane = t & 31;
    __shared__ float sctx[CSZ];
    __shared__ float shid[HIDN];
    __shared__ float sstat[2];
    sctx[t] = g_ctx[b * CSZ + t];
    __syncthreads();
    for (int rep = 0; rep < 2; ++rep) {
        int hidx = warp * 2 + rep;
        float acc = 0.f;
        for (int c = lane; c < CSZ; c += 32) acc += sctx[c] * fc1_w[hidx * CSZ + c];
        for (int o = 16; o > 0; o >>= 1) acc += __shfl_xor_sync(0xffffffffu, acc, o);
        if (lane == 0) shid[hidx] = acc + fc1_b[hidx];
    }
    __syncthreads();
    if (t == 0) {
        float mu = 0.f;
        for (int i = 0; i < HIDN; ++i) mu += shid[i];
        mu *= (1.0f / HIDN);
        float var = 0.f;
        for (int i = 0; i < HIDN; ++i) { float d = shid[i] - mu; var += d * d; }
        sstat[0] = mu; sstat[1] = rsqrtf(var * (1.0f / HIDN) + 1e-5f);
    }
    __syncthreads();
    if (t < HIDN)
        g_hact[b * HIDN + t] =
            fmaxf((shid[t] - sstat[0]) * sstat[1] * ln_g[t] + ln_b[t], 0.f);
}

__global__ void __launch_bounds__(256) k_head2(
    const float* __restrict__ fh_w, const float* __restrict__ fh_b)
{
    __shared__ float sH[BSZ * 17];
    int t = threadIdx.x;
    for (int i = t; i < BSZ * HIDN; i += 256)
        sH[(i >> 4) * 17 + (i & 15)] = g_hact[i];
    __syncthreads();
    int b = t & 31;
    int grp = blockIdx.x * 8 + (t >> 5);
    float h[HIDN];
#pragma unroll
    for (int i = 0; i < HIDN; ++i) h[i] = sH[b * 17 + i];

    const float4* wp = (const float4*)(fh_w + (size_t)grp * KSZ * HIDN);
    float lg[KSZ]; float mx = -1e30f;
#pragma unroll
    for (int k = 0; k < KSZ; ++k) {
        float4 w0 = wp[k * 4 + 0], w1 = wp[k * 4 + 1], w2 = wp[k * 4 + 2], w3 = wp[k * 4 + 3];
        float a = fh_b[grp * KSZ + k];
        a += h[0]*w0.x + h[1]*w0.y + h[2]*w0.z + h[3]*w0.w;
        a += h[4]*w1.x + h[5]*w1.y + h[6]*w1.z + h[7]*w1.w;
        a += h[8]*w2.x + h[9]*w2.y + h[10]*w2.z + h[11]*w2.w;
        a += h[12]*w3.x + h[13]*w3.y + h[14]*w3.z + h[15]*w3.w;
        lg[k] = a; mx = fmaxf(mx, a);
    }
    float sum = 0.f;
#pragma unroll
    for (int k = 0; k < KSZ; ++k) { lg[k] = expf(lg[k] - mx); sum += lg[k]; }
    float inv = 1.0f / sum;
    float* out = g_coeffs + (size_t)b * (CSZ * MSZ * KSZ) + grp * KSZ;
    ((float4*)out)[0] = make_float4(lg[0]*inv, lg[1]*inv, lg[2]*inv, lg[3]*inv);
    ((float4*)out)[1] = make_float4(lg[4]*inv, lg[5]*inv, lg[6]*inv, lg[7]*inv);
}

// per-plane fused resize/DFT/mask/iDFT/resize; epilogue emits bf16 hi/lo
__global__ void __launch_bounds__(256) k_spec(
    const float* __restrict__ x,
    const float* __restrict__ br, const float* __restrict__ bi)
{
    __shared__ __align__(16) float sm[10432];
    float2* B1 = (float2*)sm;
    float2* B2 = (float2*)(sm + 3584);
    float*  BX = sm + 7168;
    float4* Bq = (float4*)(sm + 7168);
    float*  sCo = sm + 10304;

    int plane = blockIdx.x;
    int t = threadIdx.x, warp = t >> 5, lane = t & 31;
    const float* xp = x + (size_t)plane * NPIX;

    for (int i = t; i < NPIX; i += 256) BX[i] = xp[i];
    if (t < 128) sCo[t] = g_coeffs[(size_t)plane * 128 + t];
    for (int i = t; i < 1792; i += 256) B1[i] = g_FwRT[i];
    __syncthreads();

    {
        float2 acc[7];
#pragma unroll
        for (int r = 0; r < 7; ++r) acc[r] = make_float2(0.f, 0.f);
        int h0 = warp * 7;
        for (int w = 0; w < HH; w += 2) {
            float2 f0 = B1[w * WFQ + lane];
            float2 f1 = B1[(w + 1) * WFQ + lane];
#pragma unroll
            for (int r = 0; r < 7; ++r) {
                float2 a = *(const float2*)&BX[(h0 + r) * HH + w];
                acc[r].x += a.x * f0.x + a.y * f1.x;
                acc[r].y += a.x * f0.y + a.y * f1.y;
            }
        }
#pragma unroll
        for (int r = 0; r < 7; ++r) B2[(h0 + r) * WFQ + lane] = acc[r];
    }
    __syncthreads();

    for (int half = 0; half < 2; ++half) {
        int ub = half * 28;
        for (int i = t; i < 14 * HH; i += 256) {
            int p = i / HH, h = i % HH;
            float2 f0 = g_Fh[(ub + 2 * p) * HH + h];
            float2 f1 = g_Fh[(ub + 2 * p + 1) * HH + h];
            Bq[i] = make_float4(f0.x, f1.x, f0.y, f1.y);
        }
        __syncthreads();
        ull ar[2] = {0, 0}, ai[2] = {0, 0};
        int p1ok = (warp + 8) < 14;
        for (int h = 0; h < HH; ++h) {
            float2 tt = B2[h * WFQ + lane];
            ull ttx = d_dup(tt.x), tty = d_dup(tt.y), ttyn = d_dup(-tt.y);
            float4 q0 = Bq[warp * HH + h];
            ull fx0 = *(ull*)&q0.x, fy0 = *(ull*)&q0.z;
            ar[0] = d_fma2(fx0, ttx, ar[0]); ar[0] = d_fma2(fy0, ttyn, ar[0]);
            ai[0] = d_fma2(fy0, ttx, ai[0]); ai[0] = d_fma2(fx0, tty, ai[0]);
            if (p1ok) {
                float4 q1 = Bq[(warp + 8) * HH + h];
                ull fx1 = *(ull*)&q1.x, fy1 = *(ull*)&q1.z;
                ar[1] = d_fma2(fx1, ttx, ar[1]); ar[1] = d_fma2(fy1, ttyn, ar[1]);
                ai[1] = d_fma2(fy1, ttx, ai[1]); ai[1] = d_fma2(fx1, tty, ai[1]);
            }
        }
#pragma unroll
        for (int pp = 0; pp < 2; ++pp) {
            int p = warp + 8 * pp;
            if (p < 14) {
                float2 re = d_unpack(ar[pp]), im = d_unpack(ai[pp]);
#pragma unroll
                for (int j = 0; j < 2; ++j) {
                    int u = ub + 2 * p + j;
                    const float* co = sCo + ((u / 14) * 4 + (lane >> 3)) * KSZ;
                    float mr = 0.f, mi = 0.f;
#pragma unroll
                    for (int k = 0; k < KSZ; ++k) {
                        int bidx = k * (HH * WFQ) + u * WFQ + lane;
                        mr += co[k] * br[bidx];
                        mi += co[k] * bi[bidx];
                    }
                    float xr = j ? re.y : re.x, xi = j ? im.y : im.x;
                    B1[u * WFQ + lane] = make_float2(xr * mr - xi * mi, xr * mi + xi * mr);
                }
            }
        }
        __syncthreads();
    }

    for (int half = 0; half < 2; ++half) {
        int hb = half * 28;
        for (int i = t; i < 14 * HH; i += 256) {
            int p = i / HH, u = i % HH;
            float2 f0 = g_Gh[(hb + 2 * p) * HH + u];
            float2 f1 = g_Gh[(hb + 2 * p + 1) * HH + u];
            Bq[i] = make_float4(f0.x, f1.x, f0.y, f1.y);
        }
        __syncthreads();
        ull ar[2] = {0, 0}, ai[2] = {0, 0};
        int p1ok = (warp + 8) < 14;
        for (int u = 0; u < HH; ++u) {
            float2 yy = B1[u * WFQ + lane];
            ull yx = d_dup(yy.x), yyp = d_dup(yy.y), yyn = d_dup(-yy.y);
            float4 q0 = Bq[warp * HH + u];
            ull fx0 = *(ull*)&q0.x, fy0 = *(ull*)&q0.z;
            ar[0] = d_fma2(fx0, yx, ar[0]); ar[0] = d_fma2(fy0, yyn, ar[0]);
            ai[0] = d_fma2(fy0, yx, ai[0]); ai[0] = d_fma2(fx0, yyp, ai[0]);
            if (p1ok) {
                float4 q1 = Bq[(warp + 8) * HH + u];
                ull fx1 = *(ull*)&q1.x, fy1 = *(ull*)&q1.z;
                ar[1] = d_fma2(fx1, yx, ar[1]); ar[1] = d_fma2(fy1, yyn, ar[1]);
                ai[1] = d_fma2(fy1, yx, ai[1]); ai[1] = d_fma2(fx1, yyp, ai[1]);
            }
        }
#pragma unroll
        for (int pp = 0; pp < 2; ++pp) {
            int p = warp + 8 * pp;
            if (p < 14) {
                float2 re = d_unpack(ar[pp]), im = d_unpack(ai[pp]);
                B2[(hb + 2 * p + 0) * WFQ + lane] = make_float2(re.x, im.x);
                B2[(hb + 2 * p + 1) * WFQ + lane] = make_float2(re.y, im.y);
            }
        }
        __syncthreads();
    }

    for (int i = t; i < 1792; i += 256) B1[i] = g_GwT[i];
    __syncthreads();
    size_t obase = (size_t)plane * NPIX;
    for (int grp = 0; grp < 2; ++grp) {
        int nr = grp ? 3 : 4;
        float a1[4] = {0.f, 0.f, 0.f, 0.f};
        float a2[4] = {0.f, 0.f, 0.f, 0.f};
        for (int v = 0; v < WFQ; ++v) {
            float2 g1 = B1[v * HH + lane];
            float2 g2 = (lane < 24) ? B1[v * HH + 32 + lane] : make_float2(0.f, 0.f);
#pragma unroll
            for (int r = 0; r < 4; ++r) {
                if (r < nr) {
                    float2 tt = B2[(warp + 8 * (grp * 4 + r)) * WFQ + v];
                    a1[r] += tt.x * g1.x - tt.y * g1.y;
                    a2[r] += tt.x * g2.x - tt.y * g2.y;
                }
            }
        }
#pragma unroll
        for (int r = 0; r < 4; ++r) {
            if (r < nr) {
                int h = warp + 8 * (grp * 4 + r);
                __nv_bfloat16 hi, lo;
                bsplit(a1[r], hi, lo);
                g_yh[obase + h * HH + lane] = hi;
                g_yl[obase + h * HH + lane] = lo;
                if (lane < 24) {
                    bsplit(a2[r], hi, lo);
                    g_yh[obase + h * HH + 32 + lane] = hi;
                    g_yl[obase + h * HH + 32 + lane] = lo;
                }
            }
        }
    }
}

// W -> bf16 hi/lo split; block 0 also zeroes BN accumulators
__global__ void k_wsplit(const float* __restrict__ W) {
    int i = blockIdx.x * blockDim.x + threadIdx.x;
    float v = W[i];
    __nv_bfloat16 hi = __float2bfloat16(v);
    __nv_bfloat16 lo = __float2bfloat16(v - __bfloat162float(hi));
    g_whl[0][i] = hi;
    g_whl[1][i] = lo;
    if (blockIdx.x == 0) { g_s1[threadIdx.x] = 0.f; g_s2[threadIdx.x] = 0.f; }
}

// ----- 1x1 conv via mma.sync bf16 split (R11 config) + BN sums, yh/yl B ----
#define KC 32
#define ASTR 40
__global__ void __launch_bounds__(256) k_conv_mma() {
    __shared__ __nv_bfloat16 cAh[128 * ASTR];
    __shared__ __nv_bfloat16 cAl[128 * ASTR];
    __shared__ __nv_bfloat16 cBh[128 * ASTR];
    __shared__ __nv_bfloat16 cBl[128 * ASTR];
    __shared__ float sS1[128], sS2[128];

    int t = threadIdx.x, wid = t >> 5, lane = t & 31;
    int p0 = blockIdx.x * 128;
    int mo = blockIdx.y * 128;
    int b  = blockIdx.z;
    const __nv_bfloat16* Yh = g_yh + (size_t)b * CSZ * NPIX;
    const __nv_bfloat16* Yl = g_yl + (size_t)b * CSZ * NPIX;
    float* Out = g_yconv + (size_t)b * CSZ * NPIX;

    int wm = (wid & 1) * 64;
    int wn = (wid >> 1) * 32;
    int qr = lane >> 2, qc = lane & 3;

    if (t < 128) { sS1[t] = 0.f; sS2[t] = 0.f; }

    float acc[16][4];
#pragma unroll
    for (int i = 0; i < 16; ++i)
#pragma unroll
        for (int j = 0; j < 4; ++j) acc[i][j] = 0.f;

    for (int kk = 0; kk < CSZ; kk += KC) {
        {
            int r = t >> 1, cg = (t & 1) * 16;
            const __nv_bfloat16* w0 = &g_whl[0][(size_t)(mo + r) * CSZ + kk + cg];
            const __nv_bfloat16* w1 = &g_whl[1][(size_t)(mo + r) * CSZ + kk + cg];
            *(uint4*)&cAh[r * ASTR + cg]     = *(const uint4*)w0;
            *(uint4*)&cAh[r * ASTR + cg + 8] = *(const uint4*)(w0 + 8);
            *(uint4*)&cAl[r * ASTR + cg]     = *(const uint4*)w1;
            *(uint4*)&cAl[r * ASTR + cg + 8] = *(const uint4*)(w1 + 8);
        }
        {
            int c = t >> 3, pg2 = (t & 7) * 16;
            const __nv_bfloat16* yh = Yh + (size_t)(kk + c) * NPIX + p0 + pg2;
            const __nv_bfloat16* yl = Yl + (size_t)(kk + c) * NPIX + p0 + pg2;
#pragma unroll
            for (int j = 0; j < 16; j += 8) {
                uint4 vh = make_uint4(0, 0, 0, 0), vl = make_uint4(0, 0, 0, 0);
                if (p0 + pg2 + j < NPIX) {
                    vh = *(const uint4*)&yh[j];
                    vl = *(const uint4*)&yl[j];
                }
                __nv_bfloat16 th[8], tl[8];
                *(uint4*)th = vh; *(uint4*)tl = vl;
#pragma unroll
                for (int e = 0; e < 8; ++e) {
                    cBh[(pg2 + j + e) * ASTR + c] = th[e];
                    cBl[(pg2 + j + e) * ASTR + c] = tl[e];
                }
            }
        }
        __syncthreads();

#pragma unroll
        for (int ks = 0; ks < 2; ++ks) {
            int cb = ks * 16 + qc * 2;
            uint32_t afh[4][4], afl[4][4];
#pragma unroll
            for (int mf = 0; mf < 4; ++mf) {
                lda_frags(cAh, ASTR, wm + mf * 16 + qr, cb, afh[mf]);
                lda_frags(cAl, ASTR, wm + mf * 16 + qr, cb, afl[mf]);
            }
            uint32_t bf[4][2];
#pragma unroll
            for (int nf = 0; nf < 4; ++nf)
                ldb_frag(cBh, ASTR, wn + nf * 8 + qr, cb, bf[nf]);
#pragma unroll
            for (int mf = 0; mf < 4; ++mf)
#pragma unroll
                for (int nf = 0; nf < 4; ++nf) {
                    mma_bf16(acc[mf * 4 + nf], afh[mf], bf[nf]);
                    mma_bf16(acc[mf * 4 + nf], afl[mf], bf[nf]);
                }
#pragma unroll
            for (int nf = 0; nf < 4; ++nf)
                ldb_frag(cBl, ASTR, wn + nf * 8 + qr, cb, bf[nf]);
#pragma unroll
            for (int mf = 0; mf < 4; ++mf)
#pragma unroll
                for (int nf = 0; nf < 4; ++nf)
                    mma_bf16(acc[mf * 4 + nf], afh[mf], bf[nf]);
        }
        __syncthreads();
    }

#pragma unroll
    for (int mf = 0; mf < 4; ++mf) {
        float s1a = 0.f, s2a = 0.f, s1b = 0.f, s2b = 0.f;
#pragma unroll
        for (int nf = 0; nf < 4; ++nf) {
            float* a = acc[mf * 4 + nf];
            int r = mo + wm + mf * 16 + qr;
            int cl = p0 + wn + nf * 8 + qc * 2;
            if (cl < NPIX) {
                *(float2*)&Out[(size_t)r * NPIX + cl] = make_float2(a[0], a[1]);
                *(float2*)&Out[(size_t)(r + 8) * NPIX + cl] = make_float2(a[2], a[3]);
            }
            s1a += a[0] + a[1]; s2a += a[0]*a[0] + a[1]*a[1];
            s1b += a[2] + a[3]; s2b += a[2]*a[2] + a[3]*a[3];
        }
#pragma unroll
        for (int o = 1; o <= 2; o <<= 1) {
            s1a += __shfl_xor_sync(0xffffffffu, s1a, o);
            s2a += __shfl_xor_sync(0xffffffffu, s2a, o);
            s1b += __shfl_xor_sync(0xffffffffu, s1b, o);
            s2b += __shfl_xor_sync(0xffffffffu, s2b, o);
        }
        if (qc == 0) {
            int lr = wm + mf * 16 + qr;
            atomicAdd(&sS1[lr], s1a); atomicAdd(&sS2[lr], s2a);
            atomicAdd(&sS1[lr + 8], s1b); atomicAdd(&sS2[lr + 8], s2b);
        }
    }
    __syncthreads();
    if (t < 128) {
        atomicAdd(&g_s1[mo + t], sS1[t]);
        atomicAdd(&g_s2[mo + t], sS2[t]);
    }
}

__global__ void k_bnfin(const float* __restrict__ bn_g, const float* __restrict__ bn_b) {
    int o = threadIdx.x;
    double N = (double)BSZ * NPIX;
    double mean = (double)g_s1[o] / N;
    double var = (double)g_s2[o] / N - mean * mean;
    float A = bn_g[o] * (float)(1.0 / sqrt(var + 1e-5));
    g_bnA[o] = A;
    g_bnB[o] = bn_b[o] - (float)mean * A;
}

__global__ void k_bnapply(float* __restrict__ out) {
    int i4 = blockIdx.x * blockDim.x + threadIdx.x;
    int c = (i4 / (NPIX / 4)) % CSZ;
    float A = g_bnA[c], Bv = g_bnB[c];
    float4 v = ((const float4*)g_yconv)[i4];
    v.x = v.x * A + Bv; v.y = v.y * A + Bv; v.z = v.z * A + Bv; v.w = v.w * A + Bv;
    ((float4*)out)[i4] = v;
}

extern "C" void kernel_launch(void* const* d_in, const int* in_sizes, int n_in,
                              void* d_out, int out_size) {
    const float* x      = (const float*)d_in[0];
    const float* fc1_w  = (const float*)d_in[1];
    const float* fc1_b  = (const float*)d_in[2];
    const float* ln_g   = (const float*)d_in[3];
    const float* ln_b   = (const float*)d_in[4];
    const float* fh_w   = (const float*)d_in[5];
    const float* fh_b   = (const float*)d_in[6];
    const float* br     = (const float*)d_in[7];
    const float* bi     = (const float*)d_in[8];
    const float* conv_w = (const float*)d_in[9];
    const float* bn_g   = (const float*)d_in[10];
    const float* bn_b   = (const float*)d_in[11];
    (void)in_sizes; (void)n_in; (void)out_size;

    k_init0<<<1, 256>>>();
    k_init1<<<40, 256>>>();
    k_ctx<<<BSZ * CSZ, 128>>>(x);
    k_head1<<<BSZ, 256>>>(fc1_w, fc1_b, ln_g, ln_b);
    k_head2<<<512, 256>>>(fh_w, fh_b);
    k_wsplit<<<256, 256>>>(conv_w);
    k_spec<<<BSZ * CSZ, 256>>>(x, br, bi);
    dim3 gc(25, 2, BSZ);
    k_conv_mma<<<gc, 256>>>();
    k_bnfin<<<1, 256>>>(bn_g, bn_b);
    k_bnapply<<<(BSZ * CSZ * NPIX) / 1024, 256>>>((float*)d_out);
}

// round 15
// speedup vs baseline: 1.1817x; 1.0944x over previous
#include <cuda_runtime.h>
#include <cuda_bf16.h>
#include <stdint.h>
#include <math.h>

#define BSZ 32
#define CSZ 256
#define HH  56
#define WFQ 32
#define WWK 62
#define NPIX 3136
#define MSZ 16
#define KSZ 8
#define HIDN 16
#define PI_D 3.141592653589793238462643383279502884

typedef unsigned long long ull;

__device__ __forceinline__ ull d_fma2(ull a, ull b, ull c) {
    ull d;
    asm("fma.rn.f32x2 %0, %1, %2, %3;" : "=l"(d) : "l"(a), "l"(b), "l"(c));
    return d;
}
__device__ __forceinline__ ull d_dup(float x) {
    ull r;
    asm("mov.b64 %0, {%1, %1};" : "=l"(r) : "f"(x));
    return r;
}
__device__ __forceinline__ float2 d_unpack(ull v) {
    float2 r;
    asm("mov.b64 {%0, %1}, %2;" : "=f"(r.x), "=f"(r.y) : "l"(v));
    return r;
}
__device__ __forceinline__ void mma_bf16(float* d, const uint32_t* a, const uint32_t* b) {
    asm("mma.sync.aligned.m16n8k16.row.col.f32.bf16.bf16.f32 "
        "{%0,%1,%2,%3}, {%4,%5,%6,%7}, {%8,%9}, {%0,%1,%2,%3};"
        : "+f"(d[0]), "+f"(d[1]), "+f"(d[2]), "+f"(d[3])
        : "r"(a[0]), "r"(a[1]), "r"(a[2]), "r"(a[3]), "r"(b[0]), "r"(b[1]));
}
__device__ __forceinline__ void bsplit(float v, __nv_bfloat16& hi, __nv_bfloat16& lo) {
    hi = __float2bfloat16(v);
    lo = __float2bfloat16(v - __bfloat162float(hi));
}
__device__ __forceinline__ void lda_frags(const __nv_bfloat16* P, int stride, int r0, int cb, uint32_t* f) {
    f[0] = *(const uint32_t*)&P[r0 * stride + cb];
    f[1] = *(const uint32_t*)&P[(r0 + 8) * stride + cb];
    f[2] = *(const uint32_t*)&P[r0 * stride + cb + 8];
    f[3] = *(const uint32_t*)&P[(r0 + 8) * stride + cb + 8];
}
__device__ __forceinline__ void ldb_frag(const __nv_bfloat16* P, int stride, int n0, int cb, uint32_t* f) {
    f[0] = *(const uint32_t*)&P[n0 * stride + cb];
    f[1] = *(const uint32_t*)&P[n0 * stride + cb + 8];
}

// ----------------------------- device scratch -------------------------------
__device__ float  g_ctx[BSZ * CSZ];
__device__ float  g_hact[BSZ * HIDN];
__device__ float  g_coeffs[BSZ * CSZ * MSZ * KSZ];
__device__ float  g_yspec[(size_t)BSZ * CSZ * NPIX];
__device__ float  g_yconv[(size_t)BSZ * CSZ * NPIX];
__device__ float  g_bnA[CSZ], g_bnB[CSZ];
__device__ float  g_s1[CSZ], g_s2[CSZ];
__device__ __nv_bfloat16 g_whl[2][CSZ * CSZ];

__device__ float2 g_FwRT[HH * WFQ];
__device__ float2 g_Fh[HH * HH];
__device__ float2 g_Gh[HH * HH];
__device__ float2 g_GwT[WFQ * HH];

__device__ double g_Rf[WWK * HH];
__device__ double g_Rb[HH * WWK];
__device__ double g_tw62r[WWK], g_tw62i[WWK];

__device__ double rz_fwd(int j, int i) {
    double s = (j + 0.5) * (56.0 / 62.0) - 0.5;
    double w = fmax(0.0, 1.0 - fabs(s - (double)i));
    double denom = 0.0;
    int i0 = (int)floor(s);
    for (int q = i0; q <= i0 + 1; ++q)
        if (q >= 0 && q < 56) denom += fmax(0.0, 1.0 - fabs(s - (double)q));
    return w / denom;
}
__device__ double rz_bwd(int j, int i) {
    double ks = 62.0 / 56.0;
    double s = (j + 0.5) * ks - 0.5;
    double w = fmax(0.0, 1.0 - fabs(s - (double)i) / ks);
    double denom = 0.0;
    int lo = (int)ceil(s - ks), hi = (int)floor(s + ks);
    if (lo < 0) lo = 0;
    if (hi > 61) hi = 61;
    for (int q = lo; q <= hi; ++q)
        denom += fmax(0.0, 1.0 - fabs(s - (double)q) / ks);
    return w / denom;
}

__global__ void k_init0() {
    int t = threadIdx.x;
    if (t < WWK) { double a = -2.0 * PI_D * t / 62.0; g_tw62r[t] = cos(a); g_tw62i[t] = sin(a); }
    for (int i = t; i < WWK * HH; i += blockDim.x) g_Rf[i] = rz_fwd(i / HH, i % HH);
    for (int i = t; i < HH * WWK; i += blockDim.x) g_Rb[i] = rz_bwd(i / WWK, i % WWK);
}

__global__ void k_init1() {
    const double SC = 1.0 / sqrt(56.0 * 62.0);
    int total = 1792 + 1792 + 3136 + 3136;
    for (int idx = blockIdx.x * blockDim.x + threadIdx.x; idx < total; idx += gridDim.x * blockDim.x) {
        if (idx < 1792) {
            int w0 = idx / WFQ, v = idx % WFQ;
            double ar = 0, ai = 0;
            for (int w = 0; w < WWK; ++w) {
                double r = g_Rf[w * HH + w0]; int m = (v * w) % WWK;
                ar += g_tw62r[m] * r; ai += g_tw62i[m] * r;
            }
            g_FwRT[w0 * WFQ + v] = make_float2((float)(ar * SC), (float)(ai * SC));
        } else if (idx < 3584) {
            int j = idx - 1792; int v = j / HH, w0 = j % HH;
            double cv = (v == 0 || v == 31) ? 1.0 : 2.0;
            double ar = 0, ai = 0;
            for (int w = 0; w < WWK; ++w) {
                double r = g_Rb[w0 * WWK + w]; int m = (v * w) % WWK;
                ar += g_tw62r[m] * r; ai -= g_tw62i[m] * r;
            }
            g_GwT[v * HH + w0] = make_float2((float)(ar * cv * SC), (float)(ai * cv * SC));
        } else if (idx < 6720) {
            int j = idx - 3584; int u = j / HH, h = j % HH;
            double a = -2.0 * PI_D * ((u * h) % HH) / 56.0;
            g_Fh[u * HH + h] = make_float2((float)cos(a), (float)sin(a));
        } else {
            int j = idx - 6720; int h = j / HH, u = j % HH;
            double a = 2.0 * PI_D * ((u * h) % HH) / 56.0;
            g_Gh[h * HH + u] = make_float2((float)cos(a), (float)(sin(a)));
        }
    }
}

__global__ void k_ctx(const float* __restrict__ x) {
    int plane = blockIdx.x;
    const float4* p = (const float4*)(x + (size_t)plane * NPIX);
    float s = 0.f;
    for (int i = threadIdx.x; i < NPIX / 4; i += blockDim.x) {
        float4 v = p[i]; s += v.x + v.y + v.z + v.w;
    }
    for (int o = 16; o > 0; o >>= 1) s += __shfl_xor_sync(0xffffffffu, s, o);
    __shared__ float red[4];
    int warp = threadIdx.x >> 5, lane = threadIdx.x & 31;
    if (lane == 0) red[warp] = s;
    __syncthreads();
    if (threadIdx.x == 0)
        g_ctx[plane] = (red[0] + red[1] + red[2] + red[3]) * (1.0f / NPIX);
}

__global__ void __launch_bounds__(256) k_head1(
    const float* __restrict__ fc1_w, const float* __restrict__ fc1_b,
    const float* __restrict__ ln_g,  const float* __restrict__ ln_b)
{
    int b = blockIdx.x, t = threadIdx.x;
    int warp = t >> 5, lane = t & 31;
    __shared__ float sctx[CSZ];
    __shared__ float shid[HIDN];
    __shared__ float sstat[2];
    sctx[t] = g_ctx[b * CSZ + t];
    __syncthreads();
    for (int rep = 0; rep < 2; ++rep) {
        int hidx = warp * 2 + rep;
        float acc = 0.f;
        for (int c = lane; c < CSZ; c += 32) acc += sctx[c] * fc1_w[hidx * CSZ + c];
        for (int o = 16; o > 0; o >>= 1) acc += __shfl_xor_sync(0xffffffffu, acc, o);
        if (lane == 0) shid[hidx] = acc + fc1_b[hidx];
    }
    __syncthreads();
    if (t == 0) {
        float mu = 0.f;
        for (int i = 0; i < HIDN; ++i) mu += shid[i];
        mu *= (1.0f / HIDN);
        float var = 0.f;
        for (int i = 0; i < HIDN; ++i) { float d = shid[i] - mu; var += d * d; }
        sstat[0] = mu; sstat[1] = rsqrtf(var * (1.0f / HIDN) + 1e-5f);
    }
    __syncthreads();
    if (t < HIDN)
        g_hact[b * HIDN + t] =
            fmaxf((shid[t] - sstat[0]) * sstat[1] * ln_g[t] + ln_b[t], 0.f);
}

__global__ void __launch_bounds__(256) k_head2(
    const float* __restrict__ fh_w, const float* __restrict__ fh_b)
{
    __shared__ float sH[BSZ * 17];
    int t = threadIdx.x;
    for (int i = t; i < BSZ * HIDN; i += 256)
        sH[(i >> 4) * 17 + (i & 15)] = g_hact[i];
    __syncthreads();
    int b = t & 31;
    int grp = blockIdx.x * 8 + (t >> 5);
    float h[HIDN];
#pragma unroll
    for (int i = 0; i < HIDN; ++i) h[i] = sH[b * 17 + i];

    const float4* wp = (const float4*)(fh_w + (size_t)grp * KSZ * HIDN);
    float lg[KSZ]; float mx = -1e30f;
#pragma unroll
    for (int k = 0; k < KSZ; ++k) {
        float4 w0 = wp[k * 4 + 0], w1 = wp[k * 4 + 1], w2 = wp[k * 4 + 2], w3 = wp[k * 4 + 3];
        float a = fh_b[grp * KSZ + k];
        a += h[0]*w0.x + h[1]*w0.y + h[2]*w0.z + h[3]*w0.w;
        a += h[4]*w1.x + h[5]*w1.y + h[6]*w1.z + h[7]*w1.w;
        a += h[8]*w2.x + h[9]*w2.y + h[10]*w2.z + h[11]*w2.w;
        a += h[12]*w3.x + h[13]*w3.y + h[14]*w3.z + h[15]*w3.w;
        lg[k] = a; mx = fmaxf(mx, a);
    }
    float sum = 0.f;
#pragma unroll
    for (int k = 0; k < KSZ; ++k) { lg[k] = expf(lg[k] - mx); sum += lg[k]; }
    float inv = 1.0f / sum;
    float* out = g_coeffs + (size_t)b * (CSZ * MSZ * KSZ) + grp * KSZ;
    ((float4*)out)[0] = make_float4(lg[0]*inv, lg[1]*inv, lg[2]*inv, lg[3]*inv);
    ((float4*)out)[1] = make_float4(lg[4]*inv, lg[5]*inv, lg[6]*inv, lg[7]*inv);
}

// per-plane fused resize/DFT/mask/iDFT/resize (scalar f32x2, inline mask)
__global__ void __launch_bounds__(256) k_spec(
    const float* __restrict__ x,
    const float* __restrict__ br, const float* __restrict__ bi)
{
    __shared__ __align__(16) float sm[10432];
    float2* B1 = (float2*)sm;
    float2* B2 = (float2*)(sm + 3584);
    float*  BX = sm + 7168;
    float4* Bq = (float4*)(sm + 7168);
    float*  sCo = sm + 10304;

    int plane = blockIdx.x;
    int t = threadIdx.x, warp = t >> 5, lane = t & 31;
    const float* xp = x + (size_t)plane * NPIX;

    for (int i = t; i < NPIX; i += 256) BX[i] = xp[i];
    if (t < 128) sCo[t] = g_coeffs[(size_t)plane * 128 + t];
    for (int i = t; i < 1792; i += 256) B1[i] = g_FwRT[i];
    __syncthreads();

    {
        float2 acc[7];
#pragma unroll
        for (int r = 0; r < 7; ++r) acc[r] = make_float2(0.f, 0.f);
        int h0 = warp * 7;
        for (int w = 0; w < HH; w += 2) {
            float2 f0 = B1[w * WFQ + lane];
            float2 f1 = B1[(w + 1) * WFQ + lane];
#pragma unroll
            for (int r = 0; r < 7; ++r) {
                float2 a = *(const float2*)&BX[(h0 + r) * HH + w];
                acc[r].x += a.x * f0.x + a.y * f1.x;
                acc[r].y += a.x * f0.y + a.y * f1.y;
            }
        }
#pragma unroll
        for (int r = 0; r < 7; ++r) B2[(h0 + r) * WFQ + lane] = acc[r];
    }
    __syncthreads();

    for (int half = 0; half < 2; ++half) {
        int ub = half * 28;
        for (int i = t; i < 14 * HH; i += 256) {
            int p = i / HH, h = i % HH;
            float2 f0 = g_Fh[(ub + 2 * p) * HH + h];
            float2 f1 = g_Fh[(ub + 2 * p + 1) * HH + h];
            Bq[i] = make_float4(f0.x, f1.x, f0.y, f1.y);
        }
        __syncthreads();
        ull ar[2] = {0, 0}, ai[2] = {0, 0};
        int p1ok = (warp + 8) < 14;
        for (int h = 0; h < HH; ++h) {
            float2 tt = B2[h * WFQ + lane];
            ull ttx = d_dup(tt.x), tty = d_dup(tt.y), ttyn = d_dup(-tt.y);
            float4 q0 = Bq[warp * HH + h];
            ull fx0 = *(ull*)&q0.x, fy0 = *(ull*)&q0.z;
            ar[0] = d_fma2(fx0, ttx, ar[0]); ar[0] = d_fma2(fy0, ttyn, ar[0]);
            ai[0] = d_fma2(fy0, ttx, ai[0]); ai[0] = d_fma2(fx0, tty, ai[0]);
            if (p1ok) {
                float4 q1 = Bq[(warp + 8) * HH + h];
                ull fx1 = *(ull*)&q1.x, fy1 = *(ull*)&q1.z;
                ar[1] = d_fma2(fx1, ttx, ar[1]); ar[1] = d_fma2(fy1, ttyn, ar[1]);
                ai[1] = d_fma2(fy1, ttx, ai[1]); ai[1] = d_fma2(fx1, tty, ai[1]);
            }
        }
#pragma unroll
        for (int pp = 0; pp < 2; ++pp) {
            int p = warp + 8 * pp;
            if (p < 14) {
                float2 re = d_unpack(ar[pp]), im = d_unpack(ai[pp]);
#pragma unroll
                for (int j = 0; j < 2; ++j) {
                    int u = ub + 2 * p + j;
                    const float* co = sCo + ((u / 14) * 4 + (lane >> 3)) * KSZ;
                    float mr = 0.f, mi = 0.f;
#pragma unroll
                    for (int k = 0; k < KSZ; ++k) {
                        int bidx = k * (HH * WFQ) + u * WFQ + lane;
                        mr += co[k] * br[bidx];
                        mi += co[k] * bi[bidx];
                    }
                    float xr = j ? re.y : re.x, xi = j ? im.y : im.x;
                    B1[u * WFQ + lane] = make_float2(xr * mr - xi * mi, xr * mi + xi * mr);
                }
            }
        }
        __syncthreads();
    }

    for (int half = 0; half < 2; ++half) {
        int hb = half * 28;
        for (int i = t; i < 14 * HH; i += 256) {
            int p = i / HH, u = i % HH;
            float2 f0 = g_Gh[(hb + 2 * p) * HH + u];
            float2 f1 = g_Gh[(hb + 2 * p + 1) * HH + u];
            Bq[i] = make_float4(f0.x, f1.x, f0.y, f1.y);
        }
        __syncthreads();
        ull ar[2] = {0, 0}, ai[2] = {0, 0};
        int p1ok = (warp + 8) < 14;
        for (int u = 0; u < HH; ++u) {
            float2 yy = B1[u * WFQ + lane];
            ull yx = d_dup(yy.x), yyp = d_dup(yy.y), yyn = d_dup(-yy.y);
            float4 q0 = Bq[warp * HH + u];
            ull fx0 = *(ull*)&q0.x, fy0 = *(ull*)&q0.z;
            ar[0] = d_fma2(fx0, yx, ar[0]); ar[0] = d_fma2(fy0, yyn, ar[0]);
            ai[0] = d_fma2(fy0, yx, ai[0]); ai[0] = d_fma2(fx0, yyp, ai[0]);
            if (p1ok) {
                float4 q1 = Bq[(warp + 8) * HH + u];
                ull fx1 = *(ull*)&q1.x, fy1 = *(ull*)&q1.z;
                ar[1] = d_fma2(fx1, yx, ar[1]); ar[1] = d_fma2(fy1, yyn, ar[1]);
                ai[1] = d_fma2(fy1, yx, ai[1]); ai[1] = d_fma2(fx1, yyp, ai[1]);
            }
        }
#pragma unroll
        for (int pp = 0; pp < 2; ++pp) {
            int p = warp + 8 * pp;
            if (p < 14) {
                float2 re = d_unpack(ar[pp]), im = d_unpack(ai[pp]);
                B2[(hb + 2 * p + 0) * WFQ + lane] = make_float2(re.x, im.x);
                B2[(hb + 2 * p + 1) * WFQ + lane] = make_float2(re.y, im.y);
            }
        }
        __syncthreads();
    }

    for (int i = t; i < 1792; i += 256) B1[i] = g_GwT[i];
    __syncthreads();
    float* outp = g_yspec + (size_t)plane * NPIX;
    for (int grp = 0; grp < 2; ++grp) {
        int nr = grp ? 3 : 4;
        float a1[4] = {0.f, 0.f, 0.f, 0.f};
        float a2[4] = {0.f, 0.f, 0.f, 0.f};
        for (int v = 0; v < WFQ; ++v) {
            float2 g1 = B1[v * HH + lane];
            float2 g2 = (lane < 24) ? B1[v * HH + 32 + lane] : make_float2(0.f, 0.f);
#pragma unroll
            for (int r = 0; r < 4; ++r) {
                if (r < nr) {
                    float2 tt = B2[(warp + 8 * (grp * 4 + r)) * WFQ + v];
                    a1[r] += tt.x * g1.x - tt.y * g1.y;
                    a2[r] += tt.x * g2.x - tt.y * g2.y;
                }
            }
        }
#pragma unroll
        for (int r = 0; r < 4; ++r) {
            if (r < nr) {
                int h = warp + 8 * (grp * 4 + r);
                outp[h * HH + lane] = a1[r];
                if (lane < 24) outp[h * HH + 32 + lane] = a2[r];
            }
        }
    }
}

// W -> bf16 hi/lo split; block 0 also zeroes BN accumulators
__global__ void k_wsplit(const float* __restrict__ W) {
    int i = blockIdx.x * blockDim.x + threadIdx.x;
    float v = W[i];
    __nv_bfloat16 hi = __float2bfloat16(v);
    __nv_bfloat16 lo = __float2bfloat16(v - __bfloat162float(hi));
    g_whl[0][i] = hi;
    g_whl[1][i] = lo;
    if (blockIdx.x == 0) { g_s1[threadIdx.x] = 0.f; g_s2[threadIdx.x] = 0.f; }
}

// ---------------- 1x1 conv via mma.sync bf16 split precision + BN sums ------
#define KC 32
#define ASTR 40
__global__ void __launch_bounds__(256) k_conv_mma() {
    __shared__ __nv_bfloat16 cAh[128 * ASTR];
    __shared__ __nv_bfloat16 cAl[128 * ASTR];
    __shared__ __nv_bfloat16 cBh[128 * ASTR];
    __shared__ __nv_bfloat16 cBl[128 * ASTR];
    __shared__ float sS1[128], sS2[128];

    int t = threadIdx.x, wid = t >> 5, lane = t & 31;
    int p0 = blockIdx.x * 128;
    int mo = blockIdx.y * 128;
    int b  = blockIdx.z;
    const float* Y = g_yspec + (size_t)b * CSZ * NPIX;
    float* Out = g_yconv + (size_t)b * CSZ * NPIX;

    int wm = (wid & 1) * 64;
    int wn = (wid >> 1) * 32;
    int qr = lane >> 2, qc = lane & 3;

    if (t < 128) { sS1[t] = 0.f; sS2[t] = 0.f; }

    float acc[16][4];
#pragma unroll
    for (int i = 0; i < 16; ++i)
#pragma unroll
        for (int j = 0; j < 4; ++j) acc[i][j] = 0.f;

    for (int kk = 0; kk < CSZ; kk += KC) {
        {
            int r = t >> 1, cg = (t & 1) * 16;
            const __nv_bfloat16* w0 = &g_whl[0][(size_t)(mo + r) * CSZ + kk + cg];
            const __nv_bfloat16* w1 = &g_whl[1][(size_t)(mo + r) * CSZ + kk + cg];
            *(uint4*)&cAh[r * ASTR + cg]     = *(const uint4*)w0;
            *(uint4*)&cAh[r * ASTR + cg + 8] = *(const uint4*)(w0 + 8);
            *(uint4*)&cAl[r * ASTR + cg]     = *(const uint4*)w1;
            *(uint4*)&cAl[r * ASTR + cg + 8] = *(const uint4*)(w1 + 8);
        }
        {
            int c = t >> 3, pg2 = (t & 7) * 16;
#pragma unroll
            for (int j = 0; j < 16; j += 4) {
                float4 v = make_float4(0.f, 0.f, 0.f, 0.f);
                if (p0 + pg2 + j < NPIX)
                    v = *(const float4*)&Y[(size_t)(kk + c) * NPIX + p0 + pg2 + j];
                float vv[4] = {v.x, v.y, v.z, v.w};
#pragma unroll
                for (int e = 0; e < 4; ++e) {
                    __nv_bfloat16 hi, lo; bsplit(vv[e], hi, lo);
                    cBh[(pg2 + j + e) * ASTR + c] = hi;
                    cBl[(pg2 + j + e) * ASTR + c] = lo;
                }
            }
        }
        __syncthreads();

#pragma unroll
        for (int ks = 0; ks < 2; ++ks) {
            int cb = ks * 16 + qc * 2;
            uint32_t afh[4][4], afl[4][4];
#pragma unroll
            for (int mf = 0; mf < 4; ++mf) {
                lda_frags(cAh, ASTR, wm + mf * 16 + qr, cb, afh[mf]);
                lda_frags(cAl, ASTR, wm + mf * 16 + qr, cb, afl[mf]);
            }
            uint32_t bf[4][2];
#pragma unroll
            for (int nf = 0; nf < 4; ++nf)
                ldb_frag(cBh, ASTR, wn + nf * 8 + qr, cb, bf[nf]);
#pragma unroll
            for (int mf = 0; mf < 4; ++mf)
#pragma unroll
                for (int nf = 0; nf < 4; ++nf) {
                    mma_bf16(acc[mf * 4 + nf], afh[mf], bf[nf]);
                    mma_bf16(acc[mf * 4 + nf], afl[mf], bf[nf]);
                }
#pragma unroll
            for (int nf = 0; nf < 4; ++nf)
                ldb_frag(cBl, ASTR, wn + nf * 8 + qr, cb, bf[nf]);
#pragma unroll
            for (int mf = 0; mf < 4; ++mf)
#pragma unroll
                for (int nf = 0; nf < 4; ++nf)
                    mma_bf16(acc[mf * 4 + nf], afh[mf], bf[nf]);
        }
        __syncthreads();
    }

    // store outputs + per-channel BN partial sums
#pragma unroll
    for (int mf = 0; mf < 4; ++mf) {
        float s1a = 0.f, s2a = 0.f, s1b = 0.f, s2b = 0.f;
#pragma unroll
        for (int nf = 0; nf < 4; ++nf) {
            float* a = acc[mf * 4 + nf];
            int r = mo + wm + mf * 16 + qr;
            int cl = p0 + wn + nf * 8 + qc * 2;
            if (cl < NPIX) {
                *(float2*)&Out[(size_t)r * NPIX + cl] = make_float2(a[0], a[1]);
                *(float2*)&Out[(size_t)(r + 8) * NPIX + cl] = make_float2(a[2], a[3]);
            }
            s1a += a[0] + a[1]; s2a += a[0]*a[0] + a[1]*a[1];
            s1b += a[2] + a[3]; s2b += a[2]*a[2] + a[3]*a[3];
        }
#pragma unroll
        for (int o = 1; o <= 2; o <<= 1) {
            s1a += __shfl_xor_sync(0xffffffffu, s1a, o);
            s2a += __shfl_xor_sync(0xffffffffu, s2a, o);
            s1b += __shfl_xor_sync(0xffffffffu, s1b, o);
            s2b += __shfl_xor_sync(0xffffffffu, s2b, o);
        }
        if (qc == 0) {
            int lr = wm + mf * 16 + qr;
            atomicAdd(&sS1[lr], s1a); atomicAdd(&sS2[lr], s2a);
            atomicAdd(&sS1[lr + 8], s1b); atomicAdd(&sS2[lr + 8], s2b);
        }
    }
    __syncthreads();
    if (t < 128) {
        atomicAdd(&g_s1[mo + t], sS1[t]);
        atomicAdd(&g_s2[mo + t], sS2[t]);
    }
}

__global__ void k_bnfin(const float* __restrict__ bn_g, const float* __restrict__ bn_b) {
    int o = threadIdx.x;
    double N = (double)BSZ * NPIX;
    double mean = (double)g_s1[o] / N;
    double var = (double)g_s2[o] / N - mean * mean;
    float A = bn_g[o] * (float)(1.0 / sqrt(var + 1e-5));
    g_bnA[o] = A;
    g_bnB[o] = bn_b[o] - (float)mean * A;
}

__global__ void k_bnapply(float* __restrict__ out) {
    int i4 = blockIdx.x * blockDim.x + threadIdx.x;
    int c = (i4 / (NPIX / 4)) % CSZ;
    float A = g_bnA[c], Bv = g_bnB[c];
    float4 v = ((const float4*)g_yconv)[i4];
    v.x = v.x * A + Bv; v.y = v.y * A + Bv; v.z = v.z * A + Bv; v.w = v.w * A + Bv;
    ((float4*)out)[i4] = v;
}

extern "C" void kernel_launch(void* const* d_in, const int* in_sizes, int n_in,
                              void* d_out, int out_size) {
    const float* x      = (const float*)d_in[0];
    const float* fc1_w  = (const float*)d_in[1];
    const float* fc1_b  = (const float*)d_in[2];
    const float* ln_g   = (const float*)d_in[3];
    const float* ln_b   = (const float*)d_in[4];
    const float* fh_w   = (const float*)d_in[5];
    const float* fh_b   = (const float*)d_in[6];
    const float* br     = (const float*)d_in[7];
    const float* bi     = (const float*)d_in[8];
    const float* conv_w = (const float*)d_in[9];
    const float* bn_g   = (const float*)d_in[10];
    const float* bn_b   = (const float*)d_in[11];
    (void)in_sizes; (void)n_in; (void)out_size;

    k_init0<<<1, 256>>>();
    k_init1<<<40, 256>>>();
    k_ctx<<<BSZ * CSZ, 128>>>(x);
    k_head1<<<BSZ, 256>>>(fc1_w, fc1_b, ln_g, ln_b);
    k_head2<<<512, 256>>>(fh_w, fh_b);
    k_wsplit<<<256, 256>>>(conv_w);
    k_spec<<<BSZ * CSZ, 256>>>(x, br, bi);
    dim3 gc(25, 2, BSZ);
    k_conv_mma<<<gc, 256>>>();
    k_bnfin<<<1, 256>>>(bn_g, bn_b);
    k_bnapply<<<(BSZ * CSZ * NPIX) / 1024, 256>>>((float*)d_out);
}

// round 16
// speedup vs baseline: 1.1861x; 1.0037x over previous
#include <cuda_runtime.h>
#include <cuda_bf16.h>
#include <stdint.h>
#include <math.h>

#define BSZ 32
#define CSZ 256
#define HH  56
#define WFQ 32
#define WWK 62
#define NPIX 3136
#define MSZ 16
#define KSZ 8
#define HIDN 16
#define PI_D 3.141592653589793238462643383279502884

typedef unsigned long long ull;

__device__ __forceinline__ ull d_fma2(ull a, ull b, ull c) {
    ull d;
    asm("fma.rn.f32x2 %0, %1, %2, %3;" : "=l"(d) : "l"(a), "l"(b), "l"(c));
    return d;
}
__device__ __forceinline__ ull d_dup(float x) {
    ull r;
    asm("mov.b64 %0, {%1, %1};" : "=l"(r) : "f"(x));
    return r;
}
__device__ __forceinline__ float2 d_unpack(ull v) {
    float2 r;
    asm("mov.b64 {%0, %1}, %2;" : "=f"(r.x), "=f"(r.y) : "l"(v));
    return r;
}
__device__ __forceinline__ void mma_bf16(float* d, const uint32_t* a, const uint32_t* b) {
    asm("mma.sync.aligned.m16n8k16.row.col.f32.bf16.bf16.f32 "
        "{%0,%1,%2,%3}, {%4,%5,%6,%7}, {%8,%9}, {%0,%1,%2,%3};"
        : "+f"(d[0]), "+f"(d[1]), "+f"(d[2]), "+f"(d[3])
        : "r"(a[0]), "r"(a[1]), "r"(a[2]), "r"(a[3]), "r"(b[0]), "r"(b[1]));
}
__device__ __forceinline__ void bsplit(float v, __nv_bfloat16& hi, __nv_bfloat16& lo) {
    hi = __float2bfloat16(v);
    lo = __float2bfloat16(v - __bfloat162float(hi));
}
__device__ __forceinline__ void lda_frags(const __nv_bfloat16* P, int stride, int r0, int cb, uint32_t* f) {
    f[0] = *(const uint32_t*)&P[r0 * stride + cb];
    f[1] = *(const uint32_t*)&P[(r0 + 8) * stride + cb];
    f[2] = *(const uint32_t*)&P[r0 * stride + cb + 8];
    f[3] = *(const uint32_t*)&P[(r0 + 8) * stride + cb + 8];
}
__device__ __forceinline__ void ldb_frag(const __nv_bfloat16* P, int stride, int n0, int cb, uint32_t* f) {
    f[0] = *(const uint32_t*)&P[n0 * stride + cb];
    f[1] = *(const uint32_t*)&P[n0 * stride + cb + 8];
}

// ----------------------------- device scratch -------------------------------
__device__ float  g_ctx[BSZ * CSZ];
__device__ float  g_hact[BSZ * HIDN];
__device__ float  g_coeffs[BSZ * CSZ * MSZ * KSZ];
__device__ float  g_yspec[(size_t)BSZ * CSZ * NPIX];
__device__ float  g_yconv[(size_t)BSZ * CSZ * NPIX];
__device__ float  g_bnA[CSZ], g_bnB[CSZ];
__device__ float  g_s1[CSZ], g_s2[CSZ];
__device__ __nv_bfloat16 g_whl[2][CSZ * CSZ];

__device__ float2 g_FwRT[HH * WFQ];
__device__ float2 g_Fh[HH * HH];
__device__ float2 g_Gh[HH * HH];
__device__ float2 g_GwT[WFQ * HH];

__device__ double g_Rf[WWK * HH];
__device__ double g_Rb[HH * WWK];
__device__ double g_tw62r[WWK], g_tw62i[WWK];

__device__ double rz_fwd(int j, int i) {
    double s = (j + 0.5) * (56.0 / 62.0) - 0.5;
    double w = fmax(0.0, 1.0 - fabs(s - (double)i));
    double denom = 0.0;
    int i0 = (int)floor(s);
    for (int q = i0; q <= i0 + 1; ++q)
        if (q >= 0 && q < 56) denom += fmax(0.0, 1.0 - fabs(s - (double)q));
    return w / denom;
}
__device__ double rz_bwd(int j, int i) {
    double ks = 62.0 / 56.0;
    double s = (j + 0.5) * ks - 0.5;
    double w = fmax(0.0, 1.0 - fabs(s - (double)i) / ks);
    double denom = 0.0;
    int lo = (int)ceil(s - ks), hi = (int)floor(s + ks);
    if (lo < 0) lo = 0;
    if (hi > 61) hi = 61;
    for (int q = lo; q <= hi; ++q)
        denom += fmax(0.0, 1.0 - fabs(s - (double)q) / ks);
    return w / denom;
}

__global__ void k_init0() {
    int t = threadIdx.x;
    if (t < WWK) { double a = -2.0 * PI_D * t / 62.0; g_tw62r[t] = cos(a); g_tw62i[t] = sin(a); }
    for (int i = t; i < WWK * HH; i += blockDim.x) g_Rf[i] = rz_fwd(i / HH, i % HH);
    for (int i = t; i < HH * WWK; i += blockDim.x) g_Rb[i] = rz_bwd(i / WWK, i % WWK);
}

__global__ void k_init1() {
    const double SC = 1.0 / sqrt(56.0 * 62.0);
    int total = 1792 + 1792 + 3136 + 3136;
    for (int idx = blockIdx.x * blockDim.x + threadIdx.x; idx < total; idx += gridDim.x * blockDim.x) {
        if (idx < 1792) {
            int w0 = idx / WFQ, v = idx % WFQ;
            double ar = 0, ai = 0;
            for (int w = 0; w < WWK; ++w) {
                double r = g_Rf[w * HH + w0]; int m = (v * w) % WWK;
                ar += g_tw62r[m] * r; ai += g_tw62i[m] * r;
            }
            g_FwRT[w0 * WFQ + v] = make_float2((float)(ar * SC), (float)(ai * SC));
        } else if (idx < 3584) {
            int j = idx - 1792; int v = j / HH, w0 = j % HH;
            double cv = (v == 0 || v == 31) ? 1.0 : 2.0;
            double ar = 0, ai = 0;
            for (int w = 0; w < WWK; ++w) {
                double r = g_Rb[w0 * WWK + w]; int m = (v * w) % WWK;
                ar += g_tw62r[m] * r; ai -= g_tw62i[m] * r;
            }
            g_GwT[v * HH + w0] = make_float2((float)(ar * cv * SC), (float)(ai * cv * SC));
        } else if (idx < 6720) {
            int j = idx - 3584; int u = j / HH, h = j % HH;
            double a = -2.0 * PI_D * ((u * h) % HH) / 56.0;
            g_Fh[u * HH + h] = make_float2((float)cos(a), (float)sin(a));
        } else {
            int j = idx - 6720; int h = j / HH, u = j % HH;
            double a = 2.0 * PI_D * ((u * h) % HH) / 56.0;
            g_Gh[h * HH + u] = make_float2((float)cos(a), (float)(sin(a)));
        }
    }
}

// GAP: one block (256 thr) per plane, batched float4 loads for MLP
__global__ void __launch_bounds__(256) k_ctx(const float* __restrict__ x) {
    int plane = blockIdx.x;
    const float4* p = (const float4*)(x + (size_t)plane * NPIX);
    int t = threadIdx.x;
    // 784 float4 per plane = 3*256 + 16
    float4 v0 = p[t];
    float4 v1 = p[t + 256];
    float4 v2 = p[t + 512];
    float4 v3 = make_float4(0.f, 0.f, 0.f, 0.f);
    if (t < 16) v3 = p[t + 768];
    float s = (v0.x + v0.y + v0.z + v0.w) + (v1.x + v1.y + v1.z + v1.w)
            + (v2.x + v2.y + v2.z + v2.w) + (v3.x + v3.y + v3.z + v3.w);
    for (int o = 16; o > 0; o >>= 1) s += __shfl_xor_sync(0xffffffffu, s, o);
    __shared__ float red[8];
    int warp = t >> 5, lane = t & 31;
    if (lane == 0) red[warp] = s;
    __syncthreads();
    if (t == 0) {
        float tot = 0.f;
#pragma unroll
        for (int i = 0; i < 8; ++i) tot += red[i];
        g_ctx[plane] = tot * (1.0f / NPIX);
    }
}

__global__ void __launch_bounds__(256) k_head1(
    const float* __restrict__ fc1_w, const float* __restrict__ fc1_b,
    const float* __restrict__ ln_g,  const float* __restrict__ ln_b)
{
    int b = blockIdx.x, t = threadIdx.x;
    int warp = t >> 5, lane = t & 31;
    __shared__ float sctx[CSZ];
    __shared__ float shid[HIDN];
    __shared__ float sstat[2];
    sctx[t] = g_ctx[b * CSZ + t];
    __syncthreads();
    for (int rep = 0; rep < 2; ++rep) {
        int hidx = warp * 2 + rep;
        float acc = 0.f;
        for (int c = lane; c < CSZ; c += 32) acc += sctx[c] * fc1_w[hidx * CSZ + c];
        for (int o = 16; o > 0; o >>= 1) acc += __shfl_xor_sync(0xffffffffu, acc, o);
        if (lane == 0) shid[hidx] = acc + fc1_b[hidx];
    }
    __syncthreads();
    if (t == 0) {
        float mu = 0.f;
        for (int i = 0; i < HIDN; ++i) mu += shid[i];
        mu *= (1.0f / HIDN);
        float var = 0.f;
        for (int i = 0; i < HIDN; ++i) { float d = shid[i] - mu; var += d * d; }
        sstat[0] = mu; sstat[1] = rsqrtf(var * (1.0f / HIDN) + 1e-5f);
    }
    __syncthreads();
    if (t < HIDN)
        g_hact[b * HIDN + t] =
            fmaxf((shid[t] - sstat[0]) * sstat[1] * ln_g[t] + ln_b[t], 0.f);
}

__global__ void __launch_bounds__(256) k_head2(
    const float* __restrict__ fh_w, const float* __restrict__ fh_b)
{
    __shared__ float sH[BSZ * 17];
    int t = threadIdx.x;
    for (int i = t; i < BSZ * HIDN; i += 256)
        sH[(i >> 4) * 17 + (i & 15)] = g_hact[i];
    __syncthreads();
    int b = t & 31;
    int grp = blockIdx.x * 8 + (t >> 5);
    float h[HIDN];
#pragma unroll
    for (int i = 0; i < HIDN; ++i) h[i] = sH[b * 17 + i];

    const float4* wp = (const float4*)(fh_w + (size_t)grp * KSZ * HIDN);
    float lg[KSZ]; float mx = -1e30f;
#pragma unroll
    for (int k = 0; k < KSZ; ++k) {
        float4 w0 = wp[k * 4 + 0], w1 = wp[k * 4 + 1], w2 = wp[k * 4 + 2], w3 = wp[k * 4 + 3];
        float a = fh_b[grp * KSZ + k];
        a += h[0]*w0.x + h[1]*w0.y + h[2]*w0.z + h[3]*w0.w;
        a += h[4]*w1.x + h[5]*w1.y + h[6]*w1.z + h[7]*w1.w;
        a += h[8]*w2.x + h[9]*w2.y + h[10]*w2.z + h[11]*w2.w;
        a += h[12]*w3.x + h[13]*w3.y + h[14]*w3.z + h[15]*w3.w;
        lg[k] = a; mx = fmaxf(mx, a);
    }
    float sum = 0.f;
#pragma unroll
    for (int k = 0; k < KSZ; ++k) { lg[k] = expf(lg[k] - mx); sum += lg[k]; }
    float inv = 1.0f / sum;
    float* out = g_coeffs + (size_t)b * (CSZ * MSZ * KSZ) + grp * KSZ;
    ((float4*)out)[0] = make_float4(lg[0]*inv, lg[1]*inv, lg[2]*inv, lg[3]*inv);
    ((float4*)out)[1] = make_float4(lg[4]*inv, lg[5]*inv, lg[6]*inv, lg[7]*inv);
}

// per-plane fused resize/DFT/mask/iDFT/resize (scalar f32x2, inline mask)
__global__ void __launch_bounds__(256) k_spec(
    const float* __restrict__ x,
    const float* __restrict__ br, const float* __restrict__ bi)
{
    __shared__ __align__(16) float sm[10432];
    float2* B1 = (float2*)sm;
    float2* B2 = (float2*)(sm + 3584);
    float*  BX = sm + 7168;
    float4* Bq = (float4*)(sm + 7168);
    float*  sCo = sm + 10304;

    int plane = blockIdx.x;
    int t = threadIdx.x, warp = t >> 5, lane = t & 31;
    const float* xp = x + (size_t)plane * NPIX;

    for (int i = t; i < NPIX; i += 256) BX[i] = xp[i];
    if (t < 128) sCo[t] = g_coeffs[(size_t)plane * 128 + t];
    for (int i = t; i < 1792; i += 256) B1[i] = g_FwRT[i];
    __syncthreads();

    {
        float2 acc[7];
#pragma unroll
        for (int r = 0; r < 7; ++r) acc[r] = make_float2(0.f, 0.f);
        int h0 = warp * 7;
        for (int w = 0; w < HH; w += 2) {
            float2 f0 = B1[w * WFQ + lane];
            float2 f1 = B1[(w + 1) * WFQ + lane];
#pragma unroll
            for (int r = 0; r < 7; ++r) {
                float2 a = *(const float2*)&BX[(h0 + r) * HH + w];
                acc[r].x += a.x * f0.x + a.y * f1.x;
                acc[r].y += a.x * f0.y + a.y * f1.y;
            }
        }
#pragma unroll
        for (int r = 0; r < 7; ++r) B2[(h0 + r) * WFQ + lane] = acc[r];
    }
    __syncthreads();

    for (int half = 0; half < 2; ++half) {
        int ub = half * 28;
        for (int i = t; i < 14 * HH; i += 256) {
            int p = i / HH, h = i % HH;
            float2 f0 = g_Fh[(ub + 2 * p) * HH + h];
            float2 f1 = g_Fh[(ub + 2 * p + 1) * HH + h];
            Bq[i] = make_float4(f0.x, f1.x, f0.y, f1.y);
        }
        __syncthreads();
        ull ar[2] = {0, 0}, ai[2] = {0, 0};
        int p1ok = (warp + 8) < 14;
        for (int h = 0; h < HH; ++h) {
            float2 tt = B2[h * WFQ + lane];
            ull ttx = d_dup(tt.x), tty = d_dup(tt.y), ttyn = d_dup(-tt.y);
            float4 q0 = Bq[warp * HH + h];
            ull fx0 = *(ull*)&q0.x, fy0 = *(ull*)&q0.z;
            ar[0] = d_fma2(fx0, ttx, ar[0]); ar[0] = d_fma2(fy0, ttyn, ar[0]);
            ai[0] = d_fma2(fy0, ttx, ai[0]); ai[0] = d_fma2(fx0, tty, ai[0]);
            if (p1ok) {
                float4 q1 = Bq[(warp + 8) * HH + h];
                ull fx1 = *(ull*)&q1.x, fy1 = *(ull*)&q1.z;
                ar[1] = d_fma2(fx1, ttx, ar[1]); ar[1] = d_fma2(fy1, ttyn, ar[1]);
                ai[1] = d_fma2(fy1, ttx, ai[1]); ai[1] = d_fma2(fx1, tty, ai[1]);
            }
        }
#pragma unroll
        for (int pp = 0; pp < 2; ++pp) {
            int p = warp + 8 * pp;
            if (p < 14) {
                float2 re = d_unpack(ar[pp]), im = d_unpack(ai[pp]);
#pragma unroll
                for (int j = 0; j < 2; ++j) {
                    int u = ub + 2 * p + j;
                    const float* co = sCo + ((u / 14) * 4 + (lane >> 3)) * KSZ;
                    float mr = 0.f, mi = 0.f;
#pragma unroll
                    for (int k = 0; k < KSZ; ++k) {
                        int bidx = k * (HH * WFQ) + u * WFQ + lane;
                        mr += co[k] * br[bidx];
                        mi += co[k] * bi[bidx];
                    }
                    float xr = j ? re.y : re.x, xi = j ? im.y : im.x;
                    B1[u * WFQ + lane] = make_float2(xr * mr - xi * mi, xr * mi + xi * mr);
                }
            }
        }
        __syncthreads();
    }

    for (int half = 0; half < 2; ++half) {
        int hb = half * 28;
        for (int i = t; i < 14 * HH; i += 256) {
            int p = i / HH, u = i % HH;
            float2 f0 = g_Gh[(hb + 2 * p) * HH + u];
            float2 f1 = g_Gh[(hb + 2 * p + 1) * HH + u];
            Bq[i] = make_float4(f0.x, f1.x, f0.y, f1.y);
        }
        __syncthreads();
        ull ar[2] = {0, 0}, ai[2] = {0, 0};
        int p1ok = (warp + 8) < 14;
        for (int u = 0; u < HH; ++u) {
            float2 yy = B1[u * WFQ + lane];
            ull yx = d_dup(yy.x), yyp = d_dup(yy.y), yyn = d_dup(-yy.y);
            float4 q0 = Bq[warp * HH + u];
            ull fx0 = *(ull*)&q0.x, fy0 = *(ull*)&q0.z;
            ar[0] = d_fma2(fx0, yx, ar[0]); ar[0] = d_fma2(fy0, yyn, ar[0]);
            ai[0] = d_fma2(fy0, yx, ai[0]); ai[0] = d_fma2(fx0, yyp, ai[0]);
            if (p1ok) {
                float4 q1 = Bq[(warp + 8) * HH + u];
                ull fx1 = *(ull*)&q1.x, fy1 = *(ull*)&q1.z;
                ar[1] = d_fma2(fx1, yx, ar[1]); ar[1] = d_fma2(fy1, yyn, ar[1]);
                ai[1] = d_fma2(fy1, yx, ai[1]); ai[1] = d_fma2(fx1, yyp, ai[1]);
            }
        }
#pragma unroll
        for (int pp = 0; pp < 2; ++pp) {
            int p = warp + 8 * pp;
            if (p < 14) {
                float2 re = d_unpack(ar[pp]), im = d_unpack(ai[pp]);
                B2[(hb + 2 * p + 0) * WFQ + lane] = make_float2(re.x, im.x);
                B2[(hb + 2 * p + 1) * WFQ + lane] = make_float2(re.y, im.y);
            }
        }
        __syncthreads();
    }

    for (int i = t; i < 1792; i += 256) B1[i] = g_GwT[i];
    __syncthreads();
    float* outp = g_yspec + (size_t)plane * NPIX;
    for (int grp = 0; grp < 2; ++grp) {
        int nr = grp ? 3 : 4;
        float a1[4] = {0.f, 0.f, 0.f, 0.f};
        float a2[4] = {0.f, 0.f, 0.f, 0.f};
        for (int v = 0; v < WFQ; ++v) {
            float2 g1 = B1[v * HH + lane];
            float2 g2 = (lane < 24) ? B1[v * HH + 32 + lane] : make_float2(0.f, 0.f);
#pragma unroll
            for (int r = 0; r < 4; ++r) {
                if (r < nr) {
                    float2 tt = B2[(warp + 8 * (grp * 4 + r)) * WFQ + v];
                    a1[r] += tt.x * g1.x - tt.y * g1.y;
                    a2[r] += tt.x * g2.x - tt.y * g2.y;
                }
            }
        }
#pragma unroll
        for (int r = 0; r < 4; ++r) {
            if (r < nr) {
                int h = warp + 8 * (grp * 4 + r);
                outp[h * HH + lane] = a1[r];
                if (lane < 24) outp[h * HH + 32 + lane] = a2[r];
            }
        }
    }
}

// W -> bf16 hi/lo split; block 0 also zeroes BN accumulators
__global__ void k_wsplit(const float* __restrict__ W) {
    int i = blockIdx.x * blockDim.x + threadIdx.x;
    float v = W[i];
    __nv_bfloat16 hi = __float2bfloat16(v);
    __nv_bfloat16 lo = __float2bfloat16(v - __bfloat162float(hi));
    g_whl[0][i] = hi;
    g_whl[1][i] = lo;
    if (blockIdx.x == 0) { g_s1[threadIdx.x] = 0.f; g_s2[threadIdx.x] = 0.f; }
}

// ---------------- 1x1 conv via mma.sync bf16 split precision + BN sums ------
#define KC 32
#define ASTR 40
__global__ void __launch_bounds__(256) k_conv_mma() {
    __shared__ __nv_bfloat16 cAh[128 * ASTR];
    __shared__ __nv_bfloat16 cAl[128 * ASTR];
    __shared__ __nv_bfloat16 cBh[128 * ASTR];
    __shared__ __nv_bfloat16 cBl[128 * ASTR];
    __shared__ float sS1[128], sS2[128];

    int t = threadIdx.x, wid = t >> 5, lane = t & 31;
    int p0 = blockIdx.x * 128;
    int mo = blockIdx.y * 128;
    int b  = blockIdx.z;
    const float* Y = g_yspec + (size_t)b * CSZ * NPIX;
    float* Out = g_yconv + (size_t)b * CSZ * NPIX;

    int wm = (wid & 1) * 64;
    int wn = (wid >> 1) * 32;
    int qr = lane >> 2, qc = lane & 3;

    if (t < 128) { sS1[t] = 0.f; sS2[t] = 0.f; }

    float acc[16][4];
#pragma unroll
    for (int i = 0; i < 16; ++i)
#pragma unroll
        for (int j = 0; j < 4; ++j) acc[i][j] = 0.f;

    for (int kk = 0; kk < CSZ; kk += KC) {
        {
            int r = t >> 1, cg = (t & 1) * 16;
            const __nv_bfloat16* w0 = &g_whl[0][(size_t)(mo + r) * CSZ + kk + cg];
            const __nv_bfloat16* w1 = &g_whl[1][(size_t)(mo + r) * CSZ + kk + cg];
            *(uint4*)&cAh[r * ASTR + cg]     = *(const uint4*)w0;
            *(uint4*)&cAh[r * ASTR + cg + 8] = *(const uint4*)(w0 + 8);
            *(uint4*)&cAl[r * ASTR + cg]     = *(const uint4*)w1;
            *(uint4*)&cAl[r * ASTR + cg + 8] = *(const uint4*)(w1 + 8);
        }
        {
            int c = t >> 3, pg2 = (t & 7) * 16;
#pragma unroll
            for (int j = 0; j < 16; j += 4) {
                float4 v = make_float4(0.f, 0.f, 0.f, 0.f);
                if (p0 + pg2 + j < NPIX)
                    v = *(const float4*)&Y[(size_t)(kk + c) * NPIX + p0 + pg2 + j];
                float vv[4] = {v.x, v.y, v.z, v.w};
#pragma unroll
                for (int e = 0; e < 4; ++e) {
                    __nv_bfloat16 hi, lo; bsplit(vv[e], hi, lo);
                    cBh[(pg2 + j + e) * ASTR + c] = hi;
                    cBl[(pg2 + j + e) * ASTR + c] = lo;
                }
            }
        }
        __syncthreads();

#pragma unroll
        for (int ks = 0; ks < 2; ++ks) {
            int cb = ks * 16 + qc * 2;
            uint32_t afh[4][4], afl[4][4];
#pragma unroll
            for (int mf = 0; mf < 4; ++mf) {
                lda_frags(cAh, ASTR, wm + mf * 16 + qr, cb, afh[mf]);
                lda_frags(cAl, ASTR, wm + mf * 16 + qr, cb, afl[mf]);
            }
            uint32_t bf[4][2];
#pragma unroll
            for (int nf = 0; nf < 4; ++nf)
                ldb_frag(cBh, ASTR, wn + nf * 8 + qr, cb, bf[nf]);
#pragma unroll
            for (int mf = 0; mf < 4; ++mf)
#pragma unroll
                for (int nf = 0; nf < 4; ++nf) {
                    mma_bf16(acc[mf * 4 + nf], afh[mf], bf[nf]);
                    mma_bf16(acc[mf * 4 + nf], afl[mf], bf[nf]);
                }
#pragma unroll
            for (int nf = 0; nf < 4; ++nf)
                ldb_frag(cBl, ASTR, wn + nf * 8 + qr, cb, bf[nf]);
#pragma unroll
            for (int mf = 0; mf < 4; ++mf)
#pragma unroll
                for (int nf = 0; nf < 4; ++nf)
                    mma_bf16(acc[mf * 4 + nf], afh[mf], bf[nf]);
        }
        __syncthreads();
    }

    // store outputs + per-channel BN partial sums
#pragma unroll
    for (int mf = 0; mf < 4; ++mf) {
        float s1a = 0.f, s2a = 0.f, s1b = 0.f, s2b = 0.f;
#pragma unroll
        for (int nf = 0; nf < 4; ++nf) {
            float* a = acc[mf * 4 + nf];
            int r = mo + wm + mf * 16 + qr;
            int cl = p0 + wn + nf * 8 + qc * 2;
            if (cl < NPIX) {
                *(float2*)&Out[(size_t)r * NPIX + cl] = make_float2(a[0], a[1]);
                *(float2*)&Out[(size_t)(r + 8) * NPIX + cl] = make_float2(a[2], a[3]);
            }
            s1a += a[0] + a[1]; s2a += a[0]*a[0] + a[1]*a[1];
            s1b += a[2] + a[3]; s2b += a[2]*a[2] + a[3]*a[3];
        }
#pragma unroll
        for (int o = 1; o <= 2; o <<= 1) {
            s1a += __shfl_xor_sync(0xffffffffu, s1a, o);
            s2a += __shfl_xor_sync(0xffffffffu, s2a, o);
            s1b += __shfl_xor_sync(0xffffffffu, s1b, o);
            s2b += __shfl_xor_sync(0xffffffffu, s2b, o);
        }
        if (qc == 0) {
            int lr = wm + mf * 16 + qr;
            atomicAdd(&sS1[lr], s1a); atomicAdd(&sS2[lr], s2a);
            atomicAdd(&sS1[lr + 8], s1b); atomicAdd(&sS2[lr + 8], s2b);
        }
    }
    __syncthreads();
    if (t < 128) {
        atomicAdd(&g_s1[mo + t], sS1[t]);
        atomicAdd(&g_s2[mo + t], sS2[t]);
    }
}

__global__ void k_bnfin(const float* __restrict__ bn_g, const float* __restrict__ bn_b) {
    int o = threadIdx.x;
    double N = (double)BSZ * NPIX;
    double mean = (double)g_s1[o] / N;
    double var = (double)g_s2[o] / N - mean * mean;
    float A = bn_g[o] * (float)(1.0 / sqrt(var + 1e-5));
    g_bnA[o] = A;
    g_bnB[o] = bn_b[o] - (float)mean * A;
}

// BN apply: one block per (b,c) row; batched float4 loads, no per-thread div
__global__ void __launch_bounds__(256) k_bnapply(float* __restrict__ out) {
    int row = blockIdx.x;                    // 0..8191 = b*CSZ + c
    int c = row & (CSZ - 1);
    float A = g_bnA[c], Bv = g_bnB[c];
    const float4* src = (const float4*)(g_yconv + (size_t)row * NPIX);
    float4* dst = (float4*)(out + (size_t)row * NPIX);
    int t = threadIdx.x;
    // 784 float4 per row = 3*256 + 16
    float4 v0 = src[t];
    float4 v1 = src[t + 256];
    float4 v2 = src[t + 512];
    float4 v3;
    bool has3 = (t < 16);
    if (has3) v3 = src[t + 768];
    v0.x = v0.x * A + Bv; v0.y = v0.y * A + Bv; v0.z = v0.z * A + Bv; v0.w = v0.w * A + Bv;
    v1.x = v1.x * A + Bv; v1.y = v1.y * A + Bv; v1.z = v1.z * A + Bv; v1.w = v1.w * A + Bv;
    v2.x = v2.x * A + Bv; v2.y = v2.y * A + Bv; v2.z = v2.z * A + Bv; v2.w = v2.w * A + Bv;
    dst[t] = v0;
    dst[t + 256] = v1;
    dst[t + 512] = v2;
    if (has3) {
        v3.x = v3.x * A + Bv; v3.y = v3.y * A + Bv; v3.z = v3.z * A + Bv; v3.w = v3.w * A + Bv;
        dst[t + 768] = v3;
    }
}

extern "C" void kernel_launch(void* const* d_in, const int* in_sizes, int n_in,
                              void* d_out, int out_size) {
    const float* x      = (const float*)d_in[0];
    const float* fc1_w  = (const float*)d_in[1];
    const float* fc1_b  = (const float*)d_in[2];
    const float* ln_g   = (const float*)d_in[3];
    const float* ln_b   = (const float*)d_in[4];
    const float* fh_w   = (const float*)d_in[5];
    const float* fh_b   = (const float*)d_in[6];
    const float* br     = (const float*)d_in[7];
    const float* bi     = (const float*)d_in[8];
    const float* conv_w = (const float*)d_in[9];
    const float* bn_g   = (const float*)d_in[10];
    const float* bn_b   = (const float*)d_in[11];
    (void)in_sizes; (void)n_in; (void)out_size;

    k_init0<<<1, 256>>>();
    k_init1<<<40, 256>>>();
    k_ctx<<<BSZ * CSZ, 256>>>(x);
    k_head1<<<BSZ, 256>>>(fc1_w, fc1_b, ln_g, ln_b);
    k_head2<<<512, 256>>>(fh_w, fh_b);
    k_wsplit<<<256, 256>>>(conv_w);
    k_spec<<<BSZ * CSZ, 256>>>(x, br, bi);
    dim3 gc(25, 2, BSZ);
    k_conv_mma<<<gc, 256>>>();
    k_bnfin<<<1, 256>>>(bn_g, bn_b);
    k_bnapply<<<BSZ * CSZ, 256>>>((float*)d_out);
}

// round 17
// speedup vs baseline: 1.2261x; 1.0337x over previous
#include <cuda_runtime.h>
#include <cuda_bf16.h>
#include <stdint.h>
#include <math.h>

#define BSZ 32
#define CSZ 256
#define HH  56
#define WFQ 32
#define WWK 62
#define NPIX 3136
#define MSZ 16
#define KSZ 8
#define HIDN 16
#define PI_D 3.141592653589793238462643383279502884

typedef unsigned long long ull;

__device__ __forceinline__ ull d_fma2(ull a, ull b, ull c) {
    ull d;
    asm("fma.rn.f32x2 %0, %1, %2, %3;" : "=l"(d) : "l"(a), "l"(b), "l"(c));
    return d;
}
__device__ __forceinline__ ull d_dup(float x) {
    ull r;
    asm("mov.b64 %0, {%1, %1};" : "=l"(r) : "f"(x));
    return r;
}
__device__ __forceinline__ float2 d_unpack(ull v) {
    float2 r;
    asm("mov.b64 {%0, %1}, %2;" : "=f"(r.x), "=f"(r.y) : "l"(v));
    return r;
}
__device__ __forceinline__ void mma_bf16(float* d, const uint32_t* a, const uint32_t* b) {
    asm("mma.sync.aligned.m16n8k16.row.col.f32.bf16.bf16.f32 "
        "{%0,%1,%2,%3}, {%4,%5,%6,%7}, {%8,%9}, {%0,%1,%2,%3};"
        : "+f"(d[0]), "+f"(d[1]), "+f"(d[2]), "+f"(d[3])
        : "r"(a[0]), "r"(a[1]), "r"(a[2]), "r"(a[3]), "r"(b[0]), "r"(b[1]));
}
__device__ __forceinline__ void bsplit(float v, __nv_bfloat16& hi, __nv_bfloat16& lo) {
    hi = __float2bfloat16(v);
    lo = __float2bfloat16(v - __bfloat162float(hi));
}
__device__ __forceinline__ void lda_frags(const __nv_bfloat16* P, int stride, int r0, int cb, uint32_t* f) {
    f[0] = *(const uint32_t*)&P[r0 * stride + cb];
    f[1] = *(const uint32_t*)&P[(r0 + 8) * stride + cb];
    f[2] = *(const uint32_t*)&P[r0 * stride + cb + 8];
    f[3] = *(const uint32_t*)&P[(r0 + 8) * stride + cb + 8];
}
__device__ __forceinline__ void ldb_frag(const __nv_bfloat16* P, int stride, int n0, int cb, uint32_t* f) {
    f[0] = *(const uint32_t*)&P[n0 * stride + cb];
    f[1] = *(const uint32_t*)&P[n0 * stride + cb + 8];
}

// ----------------------------- device scratch -------------------------------
__device__ float  g_ctx[BSZ * CSZ];
__device__ float  g_hact[BSZ * HIDN];
__device__ float  g_coeffs[BSZ * CSZ * MSZ * KSZ];
__device__ float  g_yspec[(size_t)BSZ * CSZ * NPIX];
__device__ float  g_yconv[(size_t)BSZ * CSZ * NPIX];
__device__ float  g_bnA[CSZ], g_bnB[CSZ];
__device__ float  g_s1[CSZ], g_s2[CSZ];
__device__ __nv_bfloat16 g_whl[2][CSZ * CSZ];

__device__ float2 g_FwRT[HH * WFQ];
__device__ float2 g_GwT[WFQ * HH];
__device__ float4 g_FhP[2 * 14 * HH];   // packed (cos r0, cos r1, sin r0, sin r1)
__device__ float4 g_GhP[2 * 14 * HH];

__device__ double g_Rf[WWK * HH];
__device__ double g_Rb[HH * WWK];
__device__ double g_tw62r[WWK], g_tw62i[WWK];

__device__ double rz_fwd(int j, int i) {
    double s = (j + 0.5) * (56.0 / 62.0) - 0.5;
    double w = fmax(0.0, 1.0 - fabs(s - (double)i));
    double denom = 0.0;
    int i0 = (int)floor(s);
    for (int q = i0; q <= i0 + 1; ++q)
        if (q >= 0 && q < 56) denom += fmax(0.0, 1.0 - fabs(s - (double)q));
    return w / denom;
}
__device__ double rz_bwd(int j, int i) {
    double ks = 62.0 / 56.0;
    double s = (j + 0.5) * ks - 0.5;
    double w = fmax(0.0, 1.0 - fabs(s - (double)i) / ks);
    double denom = 0.0;
    int lo = (int)ceil(s - ks), hi = (int)floor(s + ks);
    if (lo < 0) lo = 0;
    if (hi > 61) hi = 61;
    for (int q = lo; q <= hi; ++q)
        denom += fmax(0.0, 1.0 - fabs(s - (double)q) / ks);
    return w / denom;
}

__global__ void k_init0() {
    int t = threadIdx.x;
    if (t < WWK) { double a = -2.0 * PI_D * t / 62.0; g_tw62r[t] = cos(a); g_tw62i[t] = sin(a); }
    for (int i = t; i < WWK * HH; i += blockDim.x) g_Rf[i] = rz_fwd(i / HH, i % HH);
    for (int i = t; i < HH * WWK; i += blockDim.x) g_Rb[i] = rz_bwd(i / WWK, i % WWK);
}

__global__ void k_init1() {
    const double SC = 1.0 / sqrt(56.0 * 62.0);
    int total = 1792 + 1792;
    for (int idx = blockIdx.x * blockDim.x + threadIdx.x; idx < total; idx += gridDim.x * blockDim.x) {
        if (idx < 1792) {
            int w0 = idx / WFQ, v = idx % WFQ;
            double ar = 0, ai = 0;
            for (int w = 0; w < WWK; ++w) {
                double r = g_Rf[w * HH + w0]; int m = (v * w) % WWK;
                ar += g_tw62r[m] * r; ai += g_tw62i[m] * r;
            }
            g_FwRT[w0 * WFQ + v] = make_float2((float)(ar * SC), (float)(ai * SC));
        } else {
            int j = idx - 1792; int v = j / HH, w0 = j % HH;
            double cv = (v == 0 || v == 31) ? 1.0 : 2.0;
            double ar = 0, ai = 0;
            for (int w = 0; w < WWK; ++w) {
                double r = g_Rb[w0 * WWK + w]; int m = (v * w) % WWK;
                ar += g_tw62r[m] * r; ai -= g_tw62i[m] * r;
            }
            g_GwT[v * HH + w0] = make_float2((float)(ar * cv * SC), (float)(ai * cv * SC));
        }
    }
}

// packed twiddle tables for k_spec S3/S4 staging (values == original g_Fh/g_Gh packing)
__global__ void k_init2() {
    int idx = blockIdx.x * blockDim.x + threadIdx.x;
    if (idx >= 2 * 1568) return;
    int tab = idx >= 1568;                  // 0 = FhP (sign -), 1 = GhP (sign +)
    int j = idx - tab * 1568;
    int half = j / 784, rem = j % 784;
    int p = rem / HH, h = rem % HH;
    int row = half * 28 + 2 * p;
    double sgn = tab ? 2.0 : -2.0;
    double a0 = sgn * PI_D * ((row * h) % HH) / 56.0;
    double a1 = sgn * PI_D * (((row + 1) * h) % HH) / 56.0;
    float4 v = make_float4((float)cos(a0), (float)cos(a1), (float)sin(a0), (float)sin(a1));
    if (tab) g_GhP[j] = v; else g_FhP[j] = v;
}

// GAP: one block (256 thr) per plane, batched float4 loads for MLP
__global__ void __launch_bounds__(256) k_ctx(const float* __restrict__ x) {
    int plane = blockIdx.x;
    const float4* p = (const float4*)(x + (size_t)plane * NPIX);
    int t = threadIdx.x;
    float4 v0 = p[t];
    float4 v1 = p[t + 256];
    float4 v2 = p[t + 512];
    float4 v3 = make_float4(0.f, 0.f, 0.f, 0.f);
    if (t < 16) v3 = p[t + 768];
    float s = (v0.x + v0.y + v0.z + v0.w) + (v1.x + v1.y + v1.z + v1.w)
            + (v2.x + v2.y + v2.z + v2.w) + (v3.x + v3.y + v3.z + v3.w);
    for (int o = 16; o > 0; o >>= 1) s += __shfl_xor_sync(0xffffffffu, s, o);
    __shared__ float red[8];
    int warp = t >> 5, lane = t & 31;
    if (lane == 0) red[warp] = s;
    __syncthreads();
    if (t == 0) {
        float tot = 0.f;
#pragma unroll
        for (int i = 0; i < 8; ++i) tot += red[i];
        g_ctx[plane] = tot * (1.0f / NPIX);
    }
}

__global__ void __launch_bounds__(256) k_head1(
    const float* __restrict__ fc1_w, const float* __restrict__ fc1_b,
    const float* __restrict__ ln_g,  const float* __restrict__ ln_b)
{
    int b = blockIdx.x, t = threadIdx.x;
    int warp = t >> 5, lane = t & 31;
    __shared__ float sctx[CSZ];
    __shared__ float shid[HIDN];
    __shared__ float sstat[2];
    sctx[t] = g_ctx[b * CSZ + t];
    __syncthreads();
    for (int rep = 0; rep < 2; ++rep) {
        int hidx = warp * 2 + rep;
        float acc = 0.f;
        for (int c = lane; c < CSZ; c += 32) acc += sctx[c] * fc1_w[hidx * CSZ + c];
        for (int o = 16; o > 0; o >>= 1) acc += __shfl_xor_sync(0xffffffffu, acc, o);
        if (lane == 0) shid[hidx] = acc + fc1_b[hidx];
    }
    __syncthreads();
    if (t == 0) {
        float mu = 0.f;
        for (int i = 0; i < HIDN; ++i) mu += shid[i];
        mu *= (1.0f / HIDN);
        float var = 0.f;
        for (int i = 0; i < HIDN; ++i) { float d = shid[i] - mu; var += d * d; }
        sstat[0] = mu; sstat[1] = rsqrtf(var * (1.0f / HIDN) + 1e-5f);
    }
    __syncthreads();
    if (t < HIDN)
        g_hact[b * HIDN + t] =
            fmaxf((shid[t] - sstat[0]) * sstat[1] * ln_g[t] + ln_b[t], 0.f);
}

__global__ void __launch_bounds__(256) k_head2(
    const float* __restrict__ fh_w, const float* __restrict__ fh_b)
{
    __shared__ float sH[BSZ * 17];
    int t = threadIdx.x;
    for (int i = t; i < BSZ * HIDN; i += 256)
        sH[(i >> 4) * 17 + (i & 15)] = g_hact[i];
    __syncthreads();
    int b = t & 31;
    int grp = blockIdx.x * 8 + (t >> 5);
    float h[HIDN];
#pragma unroll
    for (int i = 0; i < HIDN; ++i) h[i] = sH[b * 17 + i];

    const float4* wp = (const float4*)(fh_w + (size_t)grp * KSZ * HIDN);
    float lg[KSZ]; float mx = -1e30f;
#pragma unroll
    for (int k = 0; k < KSZ; ++k) {
        float4 w0 = wp[k * 4 + 0], w1 = wp[k * 4 + 1], w2 = wp[k * 4 + 2], w3 = wp[k * 4 + 3];
        float a = fh_b[grp * KSZ + k];
        a += h[0]*w0.x + h[1]*w0.y + h[2]*w0.z + h[3]*w0.w;
        a += h[4]*w1.x + h[5]*w1.y + h[6]*w1.z + h[7]*w1.w;
        a += h[8]*w2.x + h[9]*w2.y + h[10]*w2.z + h[11]*w2.w;
        a += h[12]*w3.x + h[13]*w3.y + h[14]*w3.z + h[15]*w3.w;
        lg[k] = a; mx = fmaxf(mx, a);
    }
    float sum = 0.f;
#pragma unroll
    for (int k = 0; k < KSZ; ++k) { lg[k] = expf(lg[k] - mx); sum += lg[k]; }
    float inv = 1.0f / sum;
    float* out = g_coeffs + (size_t)b * (CSZ * MSZ * KSZ) + grp * KSZ;
    ((float4*)out)[0] = make_float4(lg[0]*inv, lg[1]*inv, lg[2]*inv, lg[3]*inv);
    ((float4*)out)[1] = make_float4(lg[4]*inv, lg[5]*inv, lg[6]*inv, lg[7]*inv);
}

// per-plane fused resize/DFT/mask/iDFT/resize (scalar f32x2, inline mask)
__global__ void __launch_bounds__(256) k_spec(
    const float* __restrict__ x,
    const float* __restrict__ br, const float* __restrict__ bi)
{
    __shared__ __align__(16) float sm[10432];
    float2* B1 = (float2*)sm;
    float2* B2 = (float2*)(sm + 3584);
    float*  BX = sm + 7168;
    float4* Bq = (float4*)(sm + 7168);
    float*  sCo = sm + 10304;

    int plane = blockIdx.x;
    int t = threadIdx.x, warp = t >> 5, lane = t & 31;
    const float* xp = x + (size_t)plane * NPIX;

    // stage x (float4), coeffs, FwRT (float4)
    {
        const float4* xq = (const float4*)xp;
        float4* BXq = (float4*)BX;
        BXq[t] = xq[t];
        BXq[t + 256] = xq[t + 256];
        BXq[t + 512] = xq[t + 512];
        if (t < 16) BXq[t + 768] = xq[t + 768];
        const float4* Fq = (const float4*)g_FwRT;
        float4* B1q = (float4*)B1;
        B1q[t] = Fq[t];
        B1q[t + 256] = Fq[t + 256];
        B1q[t + 512] = Fq[t + 512];
        if (t < 128) B1q[t + 768] = Fq[t + 768];
        if (t < 128) sCo[t] = g_coeffs[(size_t)plane * 128 + t];
    }
    __syncthreads();

    // S2: T1[h][v] = sum_w x[h][w] * FwRT[w][v] -> B2
    {
        float2 acc[7];
#pragma unroll
        for (int r = 0; r < 7; ++r) acc[r] = make_float2(0.f, 0.f);
        int h0 = warp * 7;
        for (int w = 0; w < HH; w += 2) {
            float2 f0 = B1[w * WFQ + lane];
            float2 f1 = B1[(w + 1) * WFQ + lane];
#pragma unroll
            for (int r = 0; r < 7; ++r) {
                float2 a = *(const float2*)&BX[(h0 + r) * HH + w];
                acc[r].x += a.x * f0.x + a.y * f1.x;
                acc[r].y += a.x * f0.y + a.y * f1.y;
            }
        }
#pragma unroll
        for (int r = 0; r < 7; ++r) B2[(h0 + r) * WFQ + lane] = acc[r];
    }
    __syncthreads();

    // S3: X = Fh @ T1 (packed twiddles), mask -> Y in B1
    for (int half = 0; half < 2; ++half) {
        int ub = half * 28;
        const float4* Fp = g_FhP + half * 784;
        for (int i = t; i < 784; i += 256) Bq[i] = Fp[i];
        __syncthreads();
        ull ar[2] = {0, 0}, ai[2] = {0, 0};
        int p1ok = (warp + 8) < 14;
        for (int h = 0; h < HH; ++h) {
            float2 tt = B2[h * WFQ + lane];
            ull ttx = d_dup(tt.x), tty = d_dup(tt.y), ttyn = d_dup(-tt.y);
            float4 q0 = Bq[warp * HH + h];
            ull fx0 = *(ull*)&q0.x, fy0 = *(ull*)&q0.z;
            ar[0] = d_fma2(fx0, ttx, ar[0]); ar[0] = d_fma2(fy0, ttyn, ar[0]);
            ai[0] = d_fma2(fy0, ttx, ai[0]); ai[0] = d_fma2(fx0, tty, ai[0]);
            if (p1ok) {
                float4 q1 = Bq[(warp + 8) * HH + h];
                ull fx1 = *(ull*)&q1.x, fy1 = *(ull*)&q1.z;
                ar[1] = d_fma2(fx1, ttx, ar[1]); ar[1] = d_fma2(fy1, ttyn, ar[1]);
                ai[1] = d_fma2(fy1, ttx, ai[1]); ai[1] = d_fma2(fx1, tty, ai[1]);
            }
        }
#pragma unroll
        for (int pp = 0; pp < 2; ++pp) {
            int p = warp + 8 * pp;
            if (p < 14) {
                float2 re = d_unpack(ar[pp]), im = d_unpack(ai[pp]);
#pragma unroll
                for (int j = 0; j < 2; ++j) {
                    int u = ub + 2 * p + j;
                    const float* co = sCo + ((u / 14) * 4 + (lane >> 3)) * KSZ;
                    float mr = 0.f, mi = 0.f;
#pragma unroll
                    for (int k = 0; k < KSZ; ++k) {
                        int bidx = k * (HH * WFQ) + u * WFQ + lane;
                        mr += co[k] * br[bidx];
                        mi += co[k] * bi[bidx];
                    }
                    float xr = j ? re.y : re.x, xi = j ? im.y : im.x;
                    B1[u * WFQ + lane] = make_float2(xr * mr - xi * mi, xr * mi + xi * mr);
                }
            }
        }
        __syncthreads();
    }

    // S4: T2 = Gh @ Y (packed twiddles) -> B2
    for (int half = 0; half < 2; ++half) {
        int hb = half * 28;
        const float4* Gp = g_GhP + half * 784;
        for (int i = t; i < 784; i += 256) Bq[i] = Gp[i];
        __syncthreads();
        ull ar[2] = {0, 0}, ai[2] = {0, 0};
        int p1ok = (warp + 8) < 14;
        for (int u = 0; u < HH; ++u) {
            float2 yy = B1[u * WFQ + lane];
            ull yx = d_dup(yy.x), yyp = d_dup(yy.y), yyn = d_dup(-yy.y);
            float4 q0 = Bq[warp * HH + u];
            ull fx0 = *(ull*)&q0.x, fy0 = *(ull*)&q0.z;
            ar[0] = d_fma2(fx0, yx, ar[0]); ar[0] = d_fma2(fy0, yyn, ar[0]);
            ai[0] = d_fma2(fy0, yx, ai[0]); ai[0] = d_fma2(fx0, yyp, ai[0]);
            if (p1ok) {
                float4 q1 = Bq[(warp + 8) * HH + u];
                ull fx1 = *(ull*)&q1.x, fy1 = *(ull*)&q1.z;
                ar[1] = d_fma2(fx1, yx, ar[1]); ar[1] = d_fma2(fy1, yyn, ar[1]);
                ai[1] = d_fma2(fy1, yx, ai[1]); ai[1] = d_fma2(fx1, yyp, ai[1]);
            }
        }
#pragma unroll
        for (int pp = 0; pp < 2; ++pp) {
            int p = warp + 8 * pp;
            if (p < 14) {
                float2 re = d_unpack(ar[pp]), im = d_unpack(ai[pp]);
                B2[(hb + 2 * p + 0) * WFQ + lane] = make_float2(re.x, im.x);
                B2[(hb + 2 * p + 1) * WFQ + lane] = make_float2(re.y, im.y);
            }
        }
        __syncthreads();
    }

    // S5: y = Re(T2 . GwT) -> g_yspec
    {
        const float4* Gq = (const float4*)g_GwT;
        float4* B1q = (float4*)B1;
        B1q[t] = Gq[t];
        B1q[t + 256] = Gq[t + 256];
        B1q[t + 512] = Gq[t + 512];
        if (t < 128) B1q[t + 768] = Gq[t + 768];
    }
    __syncthreads();
    float* outp = g_yspec + (size_t)plane * NPIX;
    for (int grp = 0; grp < 2; ++grp) {
        int nr = grp ? 3 : 4;
        float a1[4] = {0.f, 0.f, 0.f, 0.f};
        float a2[4] = {0.f, 0.f, 0.f, 0.f};
        for (int v = 0; v < WFQ; ++v) {
            float2 g1 = B1[v * HH + lane];
            float2 g2 = (lane < 24) ? B1[v * HH + 32 + lane] : make_float2(0.f, 0.f);
#pragma unroll
            for (int r = 0; r < 4; ++r) {
                if (r < nr) {
                    float2 tt = B2[(warp + 8 * (grp * 4 + r)) * WFQ + v];
                    a1[r] += tt.x * g1.x - tt.y * g1.y;
                    a2[r] += tt.x * g2.x - tt.y * g2.y;
                }
            }
        }
#pragma unroll
        for (int r = 0; r < 4; ++r) {
            if (r < nr) {
                int h = warp + 8 * (grp * 4 + r);
                outp[h * HH + lane] = a1[r];
                if (lane < 24) outp[h * HH + 32 + lane] = a2[r];
            }
        }
    }
}

// W -> bf16 hi/lo split; block 0 also zeroes BN accumulators
__global__ void k_wsplit(const float* __restrict__ W) {
    int i = blockIdx.x * blockDim.x + threadIdx.x;
    float v = W[i];
    __nv_bfloat16 hi = __float2bfloat16(v);
    __nv_bfloat16 lo = __float2bfloat16(v - __bfloat162float(hi));
    g_whl[0][i] = hi;
    g_whl[1][i] = lo;
    if (blockIdx.x == 0) { g_s1[threadIdx.x] = 0.f; g_s2[threadIdx.x] = 0.f; }
}

// ---------------- 1x1 conv via mma.sync bf16 split precision + BN sums ------
#define KC 32
#define ASTR 40
__global__ void __launch_bounds__(256) k_conv_mma() {
    __shared__ __nv_bfloat16 cAh[128 * ASTR];
    __shared__ __nv_bfloat16 cAl[128 * ASTR];
    __shared__ __nv_bfloat16 cBh[128 * ASTR];
    __shared__ __nv_bfloat16 cBl[128 * ASTR];
    __shared__ float sS1[128], sS2[128];

    int t = threadIdx.x, wid = t >> 5, lane = t & 31;
    int p0 = blockIdx.x * 128;
    int mo = blockIdx.y * 128;
    int b  = blockIdx.z;
    const float* Y = g_yspec + (size_t)b * CSZ * NPIX;
    float* Out = g_yconv + (size_t)b * CSZ * NPIX;

    int wm = (wid & 1) * 64;
    int wn = (wid >> 1) * 32;
    int qr = lane >> 2, qc = lane & 3;

    if (t < 128) { sS1[t] = 0.f; sS2[t] = 0.f; }

    float acc[16][4];
#pragma unroll
    for (int i = 0; i < 16; ++i)
#pragma unroll
        for (int j = 0; j < 4; ++j) acc[i][j] = 0.f;

    for (int kk = 0; kk < CSZ; kk += KC) {
        {
            int r = t >> 1, cg = (t & 1) * 16;
            const __nv_bfloat16* w0 = &g_whl[0][(size_t)(mo + r) * CSZ + kk + cg];
            const __nv_bfloat16* w1 = &g_whl[1][(size_t)(mo + r) * CSZ + kk + cg];
            *(uint4*)&cAh[r * ASTR + cg]     = *(const uint4*)w0;
            *(uint4*)&cAh[r * ASTR + cg + 8] = *(const uint4*)(w0 + 8);
            *(uint4*)&cAl[r * ASTR + cg]     = *(const uint4*)w1;
            *(uint4*)&cAl[r * ASTR + cg + 8] = *(const uint4*)(w1 + 8);
        }
        {
            int c = t >> 3, pg2 = (t & 7) * 16;
#pragma unroll
            for (int j = 0; j < 16; j += 4) {
                float4 v = make_float4(0.f, 0.f, 0.f, 0.f);
                if (p0 + pg2 + j < NPIX)
                    v = *(const float4*)&Y[(size_t)(kk + c) * NPIX + p0 + pg2 + j];
                float vv[4] = {v.x, v.y, v.z, v.w};
#pragma unroll
                for (int e = 0; e < 4; ++e) {
                    __nv_bfloat16 hi, lo; bsplit(vv[e], hi, lo);
                    cBh[(pg2 + j + e) * ASTR + c] = hi;
                    cBl[(pg2 + j + e) * ASTR + c] = lo;
                }
            }
        }
        __syncthreads();

#pragma unroll
        for (int ks = 0; ks < 2; ++ks) {
            int cb = ks * 16 + qc * 2;
            uint32_t afh[4][4], afl[4][4];
#pragma unroll
            for (int mf = 0; mf < 4; ++mf) {
                lda_frags(cAh, ASTR, wm + mf * 16 + qr, cb, afh[mf]);
                lda_frags(cAl, ASTR, wm + mf * 16 + qr, cb, afl[mf]);
            }
            uint32_t bf[4][2];
#pragma unroll
            for (int nf = 0; nf < 4; ++nf)
                ldb_frag(cBh, ASTR, wn + nf * 8 + qr, cb, bf[nf]);
#pragma unroll
            for (int mf = 0; mf < 4; ++mf)
#pragma unroll
                for (int nf = 0; nf < 4; ++nf) {
                    mma_bf16(acc[mf * 4 + nf], afh[mf], bf[nf]);
                    mma_bf16(acc[mf * 4 + nf], afl[mf], bf[nf]);
                }
#pragma unroll
            for (int nf = 0; nf < 4; ++nf)
                ldb_frag(cBl, ASTR, wn + nf * 8 + qr, cb, bf[nf]);
#pragma unroll
            for (int mf = 0; mf < 4; ++mf)
#pragma unroll
                for (int nf = 0; nf < 4; ++nf)
                    mma_bf16(acc[mf * 4 + nf], afh[mf], bf[nf]);
        }
        __syncthreads();
    }

    // store outputs + per-channel BN partial sums
#pragma unroll
    for (int mf = 0; mf < 4; ++mf) {
        float s1a = 0.f, s2a = 0.f, s1b = 0.f, s2b = 0.f;
#pragma unroll
        for (int nf = 0; nf < 4; ++nf) {
            float* a = acc[mf * 4 + nf];
            int r = mo + wm + mf * 16 + qr;
            int cl = p0 + wn + nf * 8 + qc * 2;
            if (cl < NPIX) {
                *(float2*)&Out[(size_t)r * NPIX + cl] = make_float2(a[0], a[1]);
                *(float2*)&Out[(size_t)(r + 8) * NPIX + cl] = make_float2(a[2], a[3]);
            }
            s1a += a[0] + a[1]; s2a += a[0]*a[0] + a[1]*a[1];
            s1b += a[2] + a[3]; s2b += a[2]*a[2] + a[3]*a[3];
        }
#pragma unroll
        for (int o = 1; o <= 2; o <<= 1) {
            s1a += __shfl_xor_sync(0xffffffffu, s1a, o);
            s2a += __shfl_xor_sync(0xffffffffu, s2a, o);
            s1b += __shfl_xor_sync(0xffffffffu, s1b, o);
            s2b += __shfl_xor_sync(0xffffffffu, s2b, o);
        }
        if (qc == 0) {
            int lr = wm + mf * 16 + qr;
            atomicAdd(&sS1[lr], s1a); atomicAdd(&sS2[lr], s2a);
            atomicAdd(&sS1[lr + 8], s1b); atomicAdd(&sS2[lr + 8], s2b);
        }
    }
    __syncthreads();
    if (t < 128) {
        atomicAdd(&g_s1[mo + t], sS1[t]);
        atomicAdd(&g_s2[mo + t], sS2[t]);
    }
}

__global__ void k_bnfin(const float* __restrict__ bn_g, const float* __restrict__ bn_b) {
    int o = threadIdx.x;
    double N = (double)BSZ * NPIX;
    double mean = (double)g_s1[o] / N;
    double var = (double)g_s2[o] / N - mean * mean;
    float A = bn_g[o] * (float)(1.0 / sqrt(var + 1e-5));
    g_bnA[o] = A;
    g_bnB[o] = bn_b[o] - (float)mean * A;
}

// BN apply: one block per (b,c) row; batched float4 loads, no per-thread div
__global__ void __launch_bounds__(256) k_bnapply(float* __restrict__ out) {
    int row = blockIdx.x;
    int c = row & (CSZ - 1);
    float A = g_bnA[c], Bv = g_bnB[c];
    const float4* src = (const float4*)(g_yconv + (size_t)row * NPIX);
    float4* dst = (float4*)(out + (size_t)row * NPIX);
    int t = threadIdx.x;
    float4 v0 = src[t];
    float4 v1 = src[t + 256];
    float4 v2 = src[t + 512];
    float4 v3;
    bool has3 = (t < 16);
    if (has3) v3 = src[t + 768];
    v0.x = v0.x * A + Bv; v0.y = v0.y * A + Bv; v0.z = v0.z * A + Bv; v0.w = v0.w * A + Bv;
    v1.x = v1.x * A + Bv; v1.y = v1.y * A + Bv; v1.z = v1.z * A + Bv; v1.w = v1.w * A + Bv;
    v2.x = v2.x * A + Bv; v2.y = v2.y * A + Bv; v2.z = v2.z * A + Bv; v2.w = v2.w * A + Bv;
    dst[t] = v0;
    dst[t + 256] = v1;
    dst[t + 512] = v2;
    if (has3) {
        v3.x = v3.x * A + Bv; v3.y = v3.y * A + Bv; v3.z = v3.z * A + Bv; v3.w = v3.w * A + Bv;
        dst[t + 768] = v3;
    }
}

extern "C" void kernel_launch(void* const* d_in, const int* in_sizes, int n_in,
                              void* d_out, int out_size) {
    const float* x      = (const float*)d_in[0];
    const float* fc1_w  = (const float*)d_in[1];
    const float* fc1_b  = (const float*)d_in[2];
    const float* ln_g   = (const float*)d_in[3];
    const float* ln_b   = (const float*)d_in[4];
    const float* fh_w   = (const float*)d_in[5];
    const float* fh_b   = (const float*)d_in[6];
    const float* br     = (const float*)d_in[7];
    const float* bi     = (const float*)d_in[8];
    const float* conv_w = (const float*)d_in[9];
    const float* bn_g   = (const float*)d_in[10];
    const float* bn_b   = (const float*)d_in[11];
    (void)in_sizes; (void)n_in; (void)out_size;

    k_init0<<<1, 256>>>();
    k_init1<<<16, 256>>>();
    k_init2<<<13, 256>>>();
    k_ctx<<<BSZ * CSZ, 256>>>(x);
    k_head1<<<BSZ, 256>>>(fc1_w, fc1_b, ln_g, ln_b);
    k_head2<<<512, 256>>>(fh_w, fh_b);
    k_wsplit<<<256, 256>>>(conv_w);
    k_spec<<<BSZ * CSZ, 256>>>(x, br, bi);
    dim3 gc(25, 2, BSZ);
    k_conv_mma<<<gc, 256>>>();
    k_bnfin<<<1, 256>>>(bn_g, bn_b);
    k_bnapply<<<BSZ * CSZ, 256>>>((float*)d_out);
}